// round 7
// baseline (speedup 1.0000x reference)
#include <cuda_runtime.h>
#include <math.h>

#define N_NODES 200000
#define N_EDGES 3200000

typedef unsigned long long u64;

// ---------------- static scratch ----------------
__device__ int    g_count [N_NODES];
__device__ int    g_rowptr[N_NODES + 1];
__device__ int    g_cursor[N_NODES];
__device__ u64    g_state [256];         // decoupled-lookback: (sum<<2)|flag
__device__ float4 g_sedge [N_EDGES];     // {src(bits), kw0, kw1, pad}
__device__ float  g_h     [N_NODES * 32];
__device__ float  g_agg1  [N_NODES * 64];

// ---------------- packed f32x2 helpers ----------------
__device__ __forceinline__ u64 splat2(float x) {
    u64 r; unsigned xi = __float_as_uint(x);
    asm("mov.b64 %0, {%1, %1};" : "=l"(r) : "r"(xi));
    return r;
}
__device__ __forceinline__ void ffma2(u64& d, u64 a, u64 b) {
    asm("fma.rn.f32x2 %0, %1, %2, %0;" : "+l"(d) : "l"(a), "l"(b));
}
__device__ __forceinline__ u64 add2(u64 a, u64 b) {
    u64 r; asm("add.rn.f32x2 %0, %1, %2;" : "=l"(r) : "l"(a), "l"(b));
    return r;
}
__device__ __forceinline__ float lo32(u64 v) { return __uint_as_float((unsigned)v); }
__device__ __forceinline__ float hi32(u64 v) { return __uint_as_float((unsigned)(v >> 32)); }
__device__ __forceinline__ u64 pack2(float lo, float hi) {
    return ((u64)__float_as_uint(hi) << 32) | (u64)__float_as_uint(lo);
}

// ---------------- CSR build ----------------
__global__ void k_hist(const int* __restrict__ dst) {
    int tid = threadIdx.x;
    if (blockIdx.x == 0 && tid < 256) g_state[tid] = 0ull;
    int e = blockIdx.x * blockDim.x + tid;
    if (e < N_EDGES) atomicAdd(&g_count[dst[e]], 1);
}

__global__ void __launch_bounds__(1024, 2) k_scan() {
    __shared__ int wsum[32];
    __shared__ int s_total;
    __shared__ int s_prefix;
    int tid = threadIdx.x, b = blockIdx.x;
    int i = b * 1024 + tid;
    int v = (i < N_NODES) ? g_count[i] : 0;
    if (i < N_NODES) g_count[i] = 0;
    int s = v;
#pragma unroll
    for (int o = 1; o < 32; o <<= 1) {
        int t = __shfl_up_sync(0xffffffffu, s, o);
        if ((tid & 31) >= o) s += t;
    }
    if ((tid & 31) == 31) wsum[tid >> 5] = s;
    __syncthreads();
    if (tid < 32) {
        int w = wsum[tid];
        int ws = w;
#pragma unroll
        for (int o = 1; o < 32; o <<= 1) {
            int t = __shfl_up_sync(0xffffffffu, ws, o);
            if (tid >= o) ws += t;
        }
        wsum[tid] = ws - w;
    }
    __syncthreads();
    int excl = s - v + wsum[tid >> 5];
    if (tid == 1023) s_total = excl + v;
    if (tid == 0) s_prefix = 0;
    __syncthreads();

    if (tid == 0) {
        u64 st = ((u64)s_total << 2) | (b == 0 ? 2ull : 1ull);
        atomicExch(&g_state[b], st);
        if (b == 0) g_rowptr[N_NODES] = N_EDGES;
    }
    if (b > 0 && tid < 32) {
        int run = 0, offset = 0;
        while (true) {
            int j = b - 1 - offset - tid;
            u64 st;
            if (j >= 0) {
                do { st = *(volatile u64*)&g_state[j]; } while ((st & 3ull) == 0ull);
            } else st = 2ull;
            unsigned pf = __ballot_sync(0xffffffffu, (st & 3ull) == 2ull);
            int contrib = (int)(st >> 2);
            if (pf) {
                int first = __ffs(pf) - 1;
                if (tid > first) contrib = 0;
#pragma unroll
                for (int o = 16; o; o >>= 1) contrib += __shfl_xor_sync(0xffffffffu, contrib, o);
                run += contrib;
                break;
            } else {
#pragma unroll
                for (int o = 16; o; o >>= 1) contrib += __shfl_xor_sync(0xffffffffu, contrib, o);
                run += contrib;
                offset += 32;
            }
        }
        if (tid == 0) {
            s_prefix = run;
            atomicExch(&g_state[b], (((u64)(run + s_total)) << 2) | 2ull);
        }
    }
    __syncthreads();
    if (i < N_NODES) {
        int val = excl + s_prefix;
        g_rowptr[i] = val;
        g_cursor[i] = val;
    }
}

__global__ void k_scatter(const int* __restrict__ src, const int* __restrict__ dst,
                          const float* __restrict__ kw) {
    int e = blockIdx.x * blockDim.x + threadIdx.x;
    if (e < N_EDGES) {
        int t = dst[e];
        int p = atomicAdd(&g_cursor[t], 1);
        float4 v;
        v.x = __int_as_float(src[e]);
        v.y = kw[e];
        v.z = kw[N_EDGES + e];
        v.w = 0.f;
        g_sedge[p] = v;
    }
}

// ---------------- fused conv0 + mlp0 + L2norm: warp per node, depth-2 pipeline ----------------
__global__ void k_conv0(const float* __restrict__ x,
                        const float* __restrict__ W0, const float* __restrict__ b0) {
    __shared__ float W0s[512];
    __shared__ float b0s[32];
    int tid = threadIdx.x;
    W0s[tid] = W0[tid];
    W0s[tid + 256] = W0[tid + 256];
    if (tid < 32) b0s[tid] = b0[tid];
    __syncthreads();

    int warp = tid >> 5, lane = tid & 31;
    int node = blockIdx.x * 8 + warp;
    int f = lane & 7, sub = lane >> 3;
    int start = g_rowptr[node], end = g_rowptr[node + 1];
    float a0 = 0.f, a1 = 0.f;

    // lane owns edges start+sub, +4, +8 ... ; depth-2 pipeline: E(i+2) and v(i+1) in flight
    int e = start + sub;
    float4 E0 = make_float4(0.f, 0.f, 0.f, 0.f);
    if (e < end) E0 = g_sedge[e];
    float4 E1 = make_float4(0.f, 0.f, 0.f, 0.f);
    if (e + 4 < end) E1 = g_sedge[e + 4];
    float v0 = __ldg(&x[__float_as_int(E0.x) * 8 + f]);

    int niter = (end - start + 3) >> 2;
    for (int it = 0; it < niter; it++) {
        float4 E2 = make_float4(0.f, 0.f, 0.f, 0.f);
        if (e + 8 < end) E2 = g_sedge[e + 8];
        float v1 = __ldg(&x[__float_as_int(E1.x) * 8 + f]);
        a0 = fmaf(E0.y, v0, a0);
        a1 = fmaf(E0.z, v0, a1);
        E0 = E1; E1 = E2; v0 = v1;
        e += 4;
    }

    a0 += __shfl_xor_sync(0xffffffffu, a0, 8);
    a0 += __shfl_xor_sync(0xffffffffu, a0, 16);
    a1 += __shfl_xor_sync(0xffffffffu, a1, 8);
    a1 += __shfl_xor_sync(0xffffffffu, a1, 16);

    float val = (lane & 8) ? a1 : a0;
    float acc = b0s[lane];
#pragma unroll
    for (int k = 0; k < 16; k++) {
        float ak = __shfl_sync(0xffffffffu, val, k);
        acc = fmaf(ak, W0s[k * 32 + lane], acc);
    }
    float ss = acc * acc;
#pragma unroll
    for (int o = 16; o; o >>= 1) ss += __shfl_xor_sync(0xffffffffu, ss, o);
    float sc = 1.f / fmaxf(sqrtf(ss), 1e-12f);
    g_h[node * 32 + lane] = acc * sc;
}

// ---------------- layer 1 conv: warp per node, lane = feature, depth-2 pipeline ----------------
__device__ __forceinline__ void ld_batch(int e, int end, float4* B) {
#pragma unroll
    for (int j = 0; j < 4; j++) {
        B[j] = make_float4(0.f, 0.f, 0.f, 0.f);
        if (e + j < end) B[j] = g_sedge[e + j];
    }
}

__global__ void __launch_bounds__(256, 3) k_conv1() {
    int warp = threadIdx.x >> 5, lane = threadIdx.x & 31;
    int node = blockIdx.x * 8 + warp;
    int start = g_rowptr[node], end = g_rowptr[node + 1];
    float a0 = 0.f, a1 = 0.f;
    const float* __restrict__ h = g_h;

    int e = start;
    float4 A[4], B[4];
    ld_batch(e, end, A);
    ld_batch(e + 4, end, B);
    float v0 = h[__float_as_int(A[0].x) * 32 + lane];
    float v1 = h[__float_as_int(A[1].x) * 32 + lane];
    float v2 = h[__float_as_int(A[2].x) * 32 + lane];
    float v3 = h[__float_as_int(A[3].x) * 32 + lane];

    int niter = (end - start + 3) >> 2;
    for (int it = 0; it < niter; it++) {
        float4 C[4];
        ld_batch(e + 8, end, C);
        float w0 = h[__float_as_int(B[0].x) * 32 + lane];
        float w1 = h[__float_as_int(B[1].x) * 32 + lane];
        float w2 = h[__float_as_int(B[2].x) * 32 + lane];
        float w3 = h[__float_as_int(B[3].x) * 32 + lane];

        a0 = fmaf(A[0].y, v0, a0); a1 = fmaf(A[0].z, v0, a1);
        a0 = fmaf(A[1].y, v1, a0); a1 = fmaf(A[1].z, v1, a1);
        a0 = fmaf(A[2].y, v2, a0); a1 = fmaf(A[2].z, v2, a1);
        a0 = fmaf(A[3].y, v3, a0); a1 = fmaf(A[3].z, v3, a1);

#pragma unroll
        for (int j = 0; j < 4; j++) { A[j] = B[j]; B[j] = C[j]; }
        v0 = w0; v1 = w1; v2 = w2; v3 = w3;
        e += 4;
    }

    g_agg1[node*64 + lane]      = a0;
    g_agg1[node*64 + 32 + lane] = a1;
}

// ---------------- layer 1 MLP: register-tiled SGEMM, 8x8 tile/thread ----------------
#define SM_W1 0
#define SM_A  8192
#define SM_W2 16896
#define SM_B1 25088
#define SM_B2 25216
#define SM_TOTAL 25280

__global__ void __launch_bounds__(256, 2)
k_mlp1(const float* __restrict__ W1, const float* __restrict__ b1,
       const float* __restrict__ W2, const float* __restrict__ b2,
       float* __restrict__ out) {
    extern __shared__ float sm[];
    int tid = threadIdx.x;
    int th = tid & 15;
    int tn = tid >> 4;

    for (int i = tid; i < 8192; i += 256) {
        sm[SM_W1 + i] = W1[i];
        sm[SM_W2 + i] = W2[i];
    }
    if (tid < 128) sm[SM_B1 + tid] = b1[tid];
    if (tid < 64)  sm[SM_B2 + tid] = b2[tid];

    int base = blockIdx.x * 128;
    for (int idx = tid; idx < 8192; idx += 256) {
        int g = base * 64 + idx;
        float v = (g < N_NODES * 64) ? g_agg1[g] : 0.f;
        sm[SM_A + (idx & 63) * 132 + (idx >> 6)] = v;
    }
    __syncthreads();

    u64 acc[32];
#pragma unroll
    for (int i = 0; i < 8; i++) {
        u64 bi = splat2(sm[SM_B1 + th * 8 + i]);
#pragma unroll
        for (int np = 0; np < 4; np++) acc[i * 4 + np] = bi;
    }
    {
        const float* At  = sm + SM_A + tn * 8;
        const float* W1r = sm + SM_W1 + th * 8;
#pragma unroll 4
        for (int k = 0; k < 64; k++) {
            ulonglong2 avA = *(const ulonglong2*)(At + k * 132);
            ulonglong2 avB = *(const ulonglong2*)(At + k * 132 + 4);
            u64 A2[4] = {avA.x, avA.y, avB.x, avB.y};
            float4 w0 = *(const float4*)(W1r + k * 128);
            float4 w1 = *(const float4*)(W1r + k * 128 + 4);
            u64 ws[8] = {splat2(w0.x), splat2(w0.y), splat2(w0.z), splat2(w0.w),
                         splat2(w1.x), splat2(w1.y), splat2(w1.z), splat2(w1.w)};
#pragma unroll
            for (int i = 0; i < 8; i++)
#pragma unroll
                for (int np = 0; np < 4; np++)
                    ffma2(acc[i * 4 + np], A2[np], ws[i]);
        }
    }
    __syncthreads();

    {
        float* Zs = sm;
#pragma unroll
        for (int i = 0; i < 8; i++) {
            int hh = th * 8 + i;
            int rot = hh >> 3;
            float* row = Zs + hh * 132;
#pragma unroll
            for (int np = 0; np < 4; np++) {
                u64 v = acc[i * 4 + np];
                u64 r = pack2(fmaxf(lo32(v), 0.f), fmaxf(hi32(v), 0.f));
                int q  = 2 * tn + (np >> 1);
                int qp = (q + rot) & 31;
                *(u64*)(row + qp * 4 + (np & 1) * 2) = r;
            }
        }
    }
    __syncthreads();

    u64 acc2[16];
#pragma unroll
    for (int o = 0; o < 4; o++) {
        u64 bo = splat2(sm[SM_B2 + th * 4 + o]);
#pragma unroll
        for (int np = 0; np < 4; np++) acc2[o * 4 + np] = bo;
    }
    {
        const float* Zs  = sm;
        const float* W2r = sm + SM_W2 + th * 4;
#pragma unroll 4
        for (int k = 0; k < 128; k++) {
            int rot = k >> 3;
            const float* row = Zs + k * 132;
            ulonglong2 z0 = *(const ulonglong2*)(row + (((2 * tn + 0 + rot) & 31) << 2));
            ulonglong2 z1 = *(const ulonglong2*)(row + (((2 * tn + 1 + rot) & 31) << 2));
            u64 A2[4] = {z0.x, z0.y, z1.x, z1.y};
            float4 wv = *(const float4*)(W2r + k * 64);
            u64 ws[4] = {splat2(wv.x), splat2(wv.y), splat2(wv.z), splat2(wv.w)};
#pragma unroll
            for (int o = 0; o < 4; o++)
#pragma unroll
                for (int np = 0; np < 4; np++)
                    ffma2(acc2[o * 4 + np], A2[np], ws[o]);
        }
    }

    u64 ss2[4];
#pragma unroll
    for (int np = 0; np < 4; np++) ss2[np] = 0ull;
#pragma unroll
    for (int o = 0; o < 4; o++)
#pragma unroll
        for (int np = 0; np < 4; np++)
            ffma2(ss2[np], acc2[o * 4 + np], acc2[o * 4 + np]);
#pragma unroll
    for (int m = 1; m < 16; m <<= 1)
#pragma unroll
        for (int np = 0; np < 4; np++)
            ss2[np] = add2(ss2[np], __shfl_xor_sync(0xffffffffu, ss2[np], m));

#pragma unroll
    for (int np = 0; np < 4; np++) {
        float se = 1.f / fmaxf(sqrtf(lo32(ss2[np])), 1e-12f);
        float so = 1.f / fmaxf(sqrtf(hi32(ss2[np])), 1e-12f);
        int ne = base + tn * 8 + 2 * np;
        if (ne < N_NODES) {
            float4 v;
            v.x = lo32(acc2[0 * 4 + np]) * se;
            v.y = lo32(acc2[1 * 4 + np]) * se;
            v.z = lo32(acc2[2 * 4 + np]) * se;
            v.w = lo32(acc2[3 * 4 + np]) * se;
            *(float4*)(out + ne * 64 + th * 4) = v;
        }
        if (ne + 1 < N_NODES) {
            float4 v;
            v.x = hi32(acc2[0 * 4 + np]) * so;
            v.y = hi32(acc2[1 * 4 + np]) * so;
            v.z = hi32(acc2[2 * 4 + np]) * so;
            v.w = hi32(acc2[3 * 4 + np]) * so;
            *(float4*)(out + (ne + 1) * 64 + th * 4) = v;
        }
    }
}

// ---------------- launch ----------------
extern "C" void kernel_launch(void* const* d_in, const int* in_sizes, int n_in,
                              void* d_out, int out_size) {
    const float* x  = (const float*)d_in[0];
    const int*   ei = (const int*)  d_in[1];
    const float* kw = (const float*)d_in[2];
    const float* W0 = (const float*)d_in[3];
    const float* b0 = (const float*)d_in[4];
    const float* W1 = (const float*)d_in[5];
    const float* b1 = (const float*)d_in[6];
    const float* W2 = (const float*)d_in[7];
    const float* b2 = (const float*)d_in[8];
    float* out = (float*)d_out;
    const int* src = ei;
    const int* dst = ei + N_EDGES;

    cudaFuncSetAttribute(k_mlp1, cudaFuncAttributeMaxDynamicSharedMemorySize,
                         SM_TOTAL * (int)sizeof(float));

    k_hist   <<<(N_EDGES + 255) / 256, 256>>>(dst);              // launch 0
    k_scan   <<<(N_NODES + 1023) / 1024, 1024>>>();              // launch 1
    k_scatter<<<(N_EDGES + 255) / 256, 256>>>(src, dst, kw);     // launch 2
    k_conv0  <<<N_NODES / 8, 256>>>(x, W0, b0);                  // launch 3 (ncu window)
    k_conv1  <<<N_NODES / 8, 256>>>();                           // launch 4
    k_mlp1   <<<(N_NODES + 127) / 128, 256, SM_TOTAL * (int)sizeof(float)>>>(W1, b1, W2, b2, out);
}

// round 8
// speedup vs baseline: 1.0868x; 1.0868x over previous
#include <cuda_runtime.h>
#include <math.h>

#define N_NODES 200000
#define N_EDGES 3200000
#define SCAN_BLOCKS 196   // ceil(200000/1024); must stay <= co-resident capacity (2/SM * 148)

typedef unsigned long long u64;

// ---------------- static scratch ----------------
__device__ int      g_count [N_NODES];
__device__ int      g_rowptr[N_NODES + 1];
__device__ int      g_cursor[N_NODES];
__device__ u64      g_state [256];        // decoupled-lookback: (sum<<2)|flag
__device__ unsigned g_arrive;             // grid-barrier ticket counter (monotonic)
__device__ float4   g_sedge [N_EDGES];    // {src(bits), kw0, kw1, pad}
__device__ float    g_h     [N_NODES * 32];
__device__ float    g_agg1  [N_NODES * 64];

// ---------------- packed f32x2 helpers ----------------
__device__ __forceinline__ u64 splat2(float x) {
    u64 r; unsigned xi = __float_as_uint(x);
    asm("mov.b64 %0, {%1, %1};" : "=l"(r) : "r"(xi));
    return r;
}
__device__ __forceinline__ void ffma2(u64& d, u64 a, u64 b) {
    asm("fma.rn.f32x2 %0, %1, %2, %0;" : "+l"(d) : "l"(a), "l"(b));
}
__device__ __forceinline__ u64 add2(u64 a, u64 b) {
    u64 r; asm("add.rn.f32x2 %0, %1, %2;" : "=l"(r) : "l"(a), "l"(b));
    return r;
}
__device__ __forceinline__ float lo32(u64 v) { return __uint_as_float((unsigned)v); }
__device__ __forceinline__ float hi32(u64 v) { return __uint_as_float((unsigned)(v >> 32)); }
__device__ __forceinline__ u64 pack2(float lo, float hi) {
    return ((u64)__float_as_uint(hi) << 32) | (u64)__float_as_uint(lo);
}

// ---------------- fused hist + scan (cooperative, one launch) ----------------
// Phase 1: grid-stride histogram of dst into g_count (g_count zeroed by phase 2 of
// the PREVIOUS call; zero at module load). Phase 2 (after grid barrier): exclusive
// scan via decoupled lookback -> g_rowptr/g_cursor, re-zeroing g_count behind itself.
__global__ void __launch_bounds__(1024, 2) k_histscan(const int* __restrict__ dst) {
    int tid = threadIdx.x, b = blockIdx.x;
    const int G = SCAN_BLOCKS;

    if (b == 0 && tid < 256) g_state[tid] = 0ull;   // reset lookback state for this call

    // --- phase 1: histogram ---
    for (int e = b * 1024 + tid; e < N_EDGES; e += G * 1024)
        atomicAdd(&g_count[dst[e]], 1);

    // --- grid barrier (epoch tickets; counter is monotonic across calls) ---
    __threadfence();
    __syncthreads();
    if (tid == 0) {
        unsigned t = atomicAdd(&g_arrive, 1u);
        unsigned target = (t / (unsigned)G + 1u) * (unsigned)G;
        while (atomicAdd(&g_arrive, 0u) < target) { }
    }
    __syncthreads();

    // --- phase 2: scan (identical math to previous k_scan) ---
    __shared__ int wsum[32];
    __shared__ int s_total;
    __shared__ int s_prefix;
    int i = b * 1024 + tid;
    int v = (i < N_NODES) ? g_count[i] : 0;
    if (i < N_NODES) g_count[i] = 0;      // clean for next call
    int s = v;
#pragma unroll
    for (int o = 1; o < 32; o <<= 1) {
        int t = __shfl_up_sync(0xffffffffu, s, o);
        if ((tid & 31) >= o) s += t;
    }
    if ((tid & 31) == 31) wsum[tid >> 5] = s;
    __syncthreads();
    if (tid < 32) {
        int w = wsum[tid];
        int ws = w;
#pragma unroll
        for (int o = 1; o < 32; o <<= 1) {
            int t = __shfl_up_sync(0xffffffffu, ws, o);
            if (tid >= o) ws += t;
        }
        wsum[tid] = ws - w;
    }
    __syncthreads();
    int excl = s - v + wsum[tid >> 5];
    if (tid == 1023) s_total = excl + v;
    if (tid == 0) s_prefix = 0;
    __syncthreads();

    if (tid == 0) {
        u64 st = ((u64)s_total << 2) | (b == 0 ? 2ull : 1ull);
        atomicExch(&g_state[b], st);
        if (b == 0) g_rowptr[N_NODES] = N_EDGES;
    }
    if (b > 0 && tid < 32) {
        int run = 0, offset = 0;
        while (true) {
            int j = b - 1 - offset - tid;
            u64 st;
            if (j >= 0) {
                do { st = *(volatile u64*)&g_state[j]; } while ((st & 3ull) == 0ull);
            } else st = 2ull;
            unsigned pf = __ballot_sync(0xffffffffu, (st & 3ull) == 2ull);
            int contrib = (int)(st >> 2);
            if (pf) {
                int first = __ffs(pf) - 1;
                if (tid > first) contrib = 0;
#pragma unroll
                for (int o = 16; o; o >>= 1) contrib += __shfl_xor_sync(0xffffffffu, contrib, o);
                run += contrib;
                break;
            } else {
#pragma unroll
                for (int o = 16; o; o >>= 1) contrib += __shfl_xor_sync(0xffffffffu, contrib, o);
                run += contrib;
                offset += 32;
            }
        }
        if (tid == 0) {
            s_prefix = run;
            atomicExch(&g_state[b], (((u64)(run + s_total)) << 2) | 2ull);
        }
    }
    __syncthreads();
    if (i < N_NODES) {
        int val = excl + s_prefix;
        g_rowptr[i] = val;
        g_cursor[i] = val;
    }
}

__global__ void k_scatter(const int* __restrict__ src, const int* __restrict__ dst,
                          const float* __restrict__ kw) {
    int e = blockIdx.x * blockDim.x + threadIdx.x;
    if (e < N_EDGES) {
        int t = dst[e];
        int p = atomicAdd(&g_cursor[t], 1);
        float4 v;
        v.x = __int_as_float(src[e]);
        v.y = kw[e];
        v.z = kw[N_EDGES + e];
        v.w = 0.f;
        g_sedge[p] = v;
    }
}

// ---------------- fused conv0 + mlp0 + L2norm: warp per node (r6 version) ----------------
__global__ void k_conv0(const float* __restrict__ x,
                        const float* __restrict__ W0, const float* __restrict__ b0) {
    __shared__ float W0s[512];
    __shared__ float b0s[32];
    int tid = threadIdx.x;
    W0s[tid] = W0[tid];
    W0s[tid + 256] = W0[tid + 256];
    if (tid < 32) b0s[tid] = b0[tid];
    __syncthreads();

    int warp = tid >> 5, lane = tid & 31;
    int node = blockIdx.x * 8 + warp;
    int f = lane & 7, sub = lane >> 3;
    int start = g_rowptr[node], end = g_rowptr[node + 1];
    float a0 = 0.f, a1 = 0.f;
    int e = start;
    for (; e + 4 <= end; e += 4) {
        float4 E = g_sedge[e + sub];
        int s = __float_as_int(E.x);
        float v = __ldg(&x[s * 8 + f]);
        a0 = fmaf(E.y, v, a0);
        a1 = fmaf(E.z, v, a1);
    }
    if (e + sub < end) {
        float4 E = g_sedge[e + sub];
        int s = __float_as_int(E.x);
        float v = __ldg(&x[s * 8 + f]);
        a0 = fmaf(E.y, v, a0);
        a1 = fmaf(E.z, v, a1);
    }
    a0 += __shfl_xor_sync(0xffffffffu, a0, 8);
    a0 += __shfl_xor_sync(0xffffffffu, a0, 16);
    a1 += __shfl_xor_sync(0xffffffffu, a1, 8);
    a1 += __shfl_xor_sync(0xffffffffu, a1, 16);

    float val = (lane & 8) ? a1 : a0;
    float acc = b0s[lane];
#pragma unroll
    for (int k = 0; k < 16; k++) {
        float ak = __shfl_sync(0xffffffffu, val, k);
        acc = fmaf(ak, W0s[k * 32 + lane], acc);
    }
    float ss = acc * acc;
#pragma unroll
    for (int o = 16; o; o >>= 1) ss += __shfl_xor_sync(0xffffffffu, ss, o);
    float sc = 1.f / fmaxf(sqrtf(ss), 1e-12f);
    g_h[node * 32 + lane] = acc * sc;
}

// ---------------- layer 1 conv: warp per node, lane = feature (r6 version) ----------------
__global__ void k_conv1() {
    int warp = threadIdx.x >> 5, lane = threadIdx.x & 31;
    int node = blockIdx.x * 8 + warp;
    int start = g_rowptr[node], end = g_rowptr[node + 1];
    float a0 = 0.f, a1 = 0.f;
    const float* __restrict__ h = g_h;
    int e = start;
    for (; e + 4 <= end; e += 4) {
        float4 E0 = g_sedge[e], E1 = g_sedge[e+1], E2 = g_sedge[e+2], E3 = g_sedge[e+3];
        float v0 = h[__float_as_int(E0.x) * 32 + lane];
        float v1 = h[__float_as_int(E1.x) * 32 + lane];
        float v2 = h[__float_as_int(E2.x) * 32 + lane];
        float v3 = h[__float_as_int(E3.x) * 32 + lane];
        a0 = fmaf(E0.y, v0, a0); a0 = fmaf(E1.y, v1, a0);
        a0 = fmaf(E2.y, v2, a0); a0 = fmaf(E3.y, v3, a0);
        a1 = fmaf(E0.z, v0, a1); a1 = fmaf(E1.z, v1, a1);
        a1 = fmaf(E2.z, v2, a1); a1 = fmaf(E3.z, v3, a1);
    }
    for (; e < end; ++e) {
        float4 E = g_sedge[e];
        float v = h[__float_as_int(E.x) * 32 + lane];
        a0 = fmaf(E.y, v, a0);
        a1 = fmaf(E.z, v, a1);
    }
    g_agg1[node*64 + lane]      = a0;
    g_agg1[node*64 + 32 + lane] = a1;
}

// ---------------- layer 1 MLP: register-tiled SGEMM, 8x8 tile/thread ----------------
#define SM_W1 0
#define SM_A  8192
#define SM_W2 16896
#define SM_B1 25088
#define SM_B2 25216
#define SM_TOTAL 25280

__global__ void __launch_bounds__(256, 2)
k_mlp1(const float* __restrict__ W1, const float* __restrict__ b1,
       const float* __restrict__ W2, const float* __restrict__ b2,
       float* __restrict__ out) {
    extern __shared__ float sm[];
    int tid = threadIdx.x;
    int th = tid & 15;
    int tn = tid >> 4;

    for (int i = tid; i < 8192; i += 256) {
        sm[SM_W1 + i] = W1[i];
        sm[SM_W2 + i] = W2[i];
    }
    if (tid < 128) sm[SM_B1 + tid] = b1[tid];
    if (tid < 64)  sm[SM_B2 + tid] = b2[tid];

    int base = blockIdx.x * 128;
    for (int idx = tid; idx < 8192; idx += 256) {
        int g = base * 64 + idx;
        float v = (g < N_NODES * 64) ? g_agg1[g] : 0.f;
        sm[SM_A + (idx & 63) * 132 + (idx >> 6)] = v;
    }
    __syncthreads();

    u64 acc[32];
#pragma unroll
    for (int i = 0; i < 8; i++) {
        u64 bi = splat2(sm[SM_B1 + th * 8 + i]);
#pragma unroll
        for (int np = 0; np < 4; np++) acc[i * 4 + np] = bi;
    }
    {
        const float* At  = sm + SM_A + tn * 8;
        const float* W1r = sm + SM_W1 + th * 8;
#pragma unroll 4
        for (int k = 0; k < 64; k++) {
            ulonglong2 avA = *(const ulonglong2*)(At + k * 132);
            ulonglong2 avB = *(const ulonglong2*)(At + k * 132 + 4);
            u64 A2[4] = {avA.x, avA.y, avB.x, avB.y};
            float4 w0 = *(const float4*)(W1r + k * 128);
            float4 w1 = *(const float4*)(W1r + k * 128 + 4);
            u64 ws[8] = {splat2(w0.x), splat2(w0.y), splat2(w0.z), splat2(w0.w),
                         splat2(w1.x), splat2(w1.y), splat2(w1.z), splat2(w1.w)};
#pragma unroll
            for (int i = 0; i < 8; i++)
#pragma unroll
                for (int np = 0; np < 4; np++)
                    ffma2(acc[i * 4 + np], A2[np], ws[i]);
        }
    }
    __syncthreads();

    {
        float* Zs = sm;
#pragma unroll
        for (int i = 0; i < 8; i++) {
            int hh = th * 8 + i;
            int rot = hh >> 3;
            float* row = Zs + hh * 132;
#pragma unroll
            for (int np = 0; np < 4; np++) {
                u64 v = acc[i * 4 + np];
                u64 r = pack2(fmaxf(lo32(v), 0.f), fmaxf(hi32(v), 0.f));
                int q  = 2 * tn + (np >> 1);
                int qp = (q + rot) & 31;
                *(u64*)(row + qp * 4 + (np & 1) * 2) = r;
            }
        }
    }
    __syncthreads();

    u64 acc2[16];
#pragma unroll
    for (int o = 0; o < 4; o++) {
        u64 bo = splat2(sm[SM_B2 + th * 4 + o]);
#pragma unroll
        for (int np = 0; np < 4; np++) acc2[o * 4 + np] = bo;
    }
    {
        const float* Zs  = sm;
        const float* W2r = sm + SM_W2 + th * 4;
#pragma unroll 4
        for (int k = 0; k < 128; k++) {
            int rot = k >> 3;
            const float* row = Zs + k * 132;
            ulonglong2 z0 = *(const ulonglong2*)(row + (((2 * tn + 0 + rot) & 31) << 2));
            ulonglong2 z1 = *(const ulonglong2*)(row + (((2 * tn + 1 + rot) & 31) << 2));
            u64 A2[4] = {z0.x, z0.y, z1.x, z1.y};
            float4 wv = *(const float4*)(W2r + k * 64);
            u64 ws[4] = {splat2(wv.x), splat2(wv.y), splat2(wv.z), splat2(wv.w)};
#pragma unroll
            for (int o = 0; o < 4; o++)
#pragma unroll
                for (int np = 0; np < 4; np++)
                    ffma2(acc2[o * 4 + np], A2[np], ws[o]);
        }
    }

    u64 ss2[4];
#pragma unroll
    for (int np = 0; np < 4; np++) ss2[np] = 0ull;
#pragma unroll
    for (int o = 0; o < 4; o++)
#pragma unroll
        for (int np = 0; np < 4; np++)
            ffma2(ss2[np], acc2[o * 4 + np], acc2[o * 4 + np]);
#pragma unroll
    for (int m = 1; m < 16; m <<= 1)
#pragma unroll
        for (int np = 0; np < 4; np++)
            ss2[np] = add2(ss2[np], __shfl_xor_sync(0xffffffffu, ss2[np], m));

#pragma unroll
    for (int np = 0; np < 4; np++) {
        float se = 1.f / fmaxf(sqrtf(lo32(ss2[np])), 1e-12f);
        float so = 1.f / fmaxf(sqrtf(hi32(ss2[np])), 1e-12f);
        int ne = base + tn * 8 + 2 * np;
        if (ne < N_NODES) {
            float4 v;
            v.x = lo32(acc2[0 * 4 + np]) * se;
            v.y = lo32(acc2[1 * 4 + np]) * se;
            v.z = lo32(acc2[2 * 4 + np]) * se;
            v.w = lo32(acc2[3 * 4 + np]) * se;
            *(float4*)(out + ne * 64 + th * 4) = v;
        }
        if (ne + 1 < N_NODES) {
            float4 v;
            v.x = hi32(acc2[0 * 4 + np]) * so;
            v.y = hi32(acc2[1 * 4 + np]) * so;
            v.z = hi32(acc2[2 * 4 + np]) * so;
            v.w = hi32(acc2[3 * 4 + np]) * so;
            *(float4*)(out + (ne + 1) * 64 + th * 4) = v;
        }
    }
}

// ---------------- launch ----------------
extern "C" void kernel_launch(void* const* d_in, const int* in_sizes, int n_in,
                              void* d_out, int out_size) {
    const float* x  = (const float*)d_in[0];
    const int*   ei = (const int*)  d_in[1];
    const float* kw = (const float*)d_in[2];
    const float* W0 = (const float*)d_in[3];
    const float* b0 = (const float*)d_in[4];
    const float* W1 = (const float*)d_in[5];
    const float* b1 = (const float*)d_in[6];
    const float* W2 = (const float*)d_in[7];
    const float* b2 = (const float*)d_in[8];
    float* out = (float*)d_out;
    const int* src = ei;
    const int* dst = ei + N_EDGES;

    cudaFuncSetAttribute(k_mlp1, cudaFuncAttributeMaxDynamicSharedMemorySize,
                         SM_TOTAL * (int)sizeof(float));

    k_histscan<<<SCAN_BLOCKS, 1024>>>(dst);                      // launch 0
    k_scatter <<<(N_EDGES + 255) / 256, 256>>>(src, dst, kw);    // launch 1
    k_conv0   <<<N_NODES / 8, 256>>>(x, W0, b0);                 // launch 2
    k_conv1   <<<N_NODES / 8, 256>>>();                          // launch 3 (ncu window)
    k_mlp1    <<<(N_NODES + 127) / 128, 256, SM_TOTAL * (int)sizeof(float)>>>(W1, b1, W2, b2, out);
}

// round 9
// speedup vs baseline: 1.1077x; 1.0192x over previous
#include <cuda_runtime.h>
#include <cuda_fp16.h>
#include <math.h>

#define N_NODES 200000
#define N_EDGES 3200000

typedef unsigned long long u64;

// ---------------- static scratch ----------------
__device__ int      g_count [N_NODES];
__device__ int      g_rowptr[N_NODES + 1];
__device__ int      g_cursor[N_NODES];
__device__ u64      g_state [256];        // decoupled-lookback: (sum<<2)|flag
__device__ float4   g_sedge [N_EDGES];    // {src(bits), kw0, kw1, pad}
__device__ __half2  g_h2    [N_NODES * 16];   // h in fp16 pairs (64B/node)
__device__ float    g_agg1  [N_NODES * 64];

// ---------------- packed f32x2 helpers ----------------
__device__ __forceinline__ u64 splat2(float x) {
    u64 r; unsigned xi = __float_as_uint(x);
    asm("mov.b64 %0, {%1, %1};" : "=l"(r) : "r"(xi));
    return r;
}
__device__ __forceinline__ void ffma2(u64& d, u64 a, u64 b) {
    asm("fma.rn.f32x2 %0, %1, %2, %0;" : "+l"(d) : "l"(a), "l"(b));
}
__device__ __forceinline__ u64 add2(u64 a, u64 b) {
    u64 r; asm("add.rn.f32x2 %0, %1, %2;" : "=l"(r) : "l"(a), "l"(b));
    return r;
}
__device__ __forceinline__ float lo32(u64 v) { return __uint_as_float((unsigned)v); }
__device__ __forceinline__ float hi32(u64 v) { return __uint_as_float((unsigned)(v >> 32)); }
__device__ __forceinline__ u64 pack2(float lo, float hi) {
    return ((u64)__float_as_uint(hi) << 32) | (u64)__float_as_uint(lo);
}

// ---------------- CSR build (r6 versions) ----------------
__global__ void k_hist(const int* __restrict__ dst) {
    int tid = threadIdx.x;
    if (blockIdx.x == 0 && tid < 256) g_state[tid] = 0ull;
    int e = blockIdx.x * blockDim.x + tid;
    if (e < N_EDGES) atomicAdd(&g_count[dst[e]], 1);
}

__global__ void __launch_bounds__(1024, 2) k_scan() {
    __shared__ int wsum[32];
    __shared__ int s_total;
    __shared__ int s_prefix;
    int tid = threadIdx.x, b = blockIdx.x;
    int i = b * 1024 + tid;
    int v = (i < N_NODES) ? g_count[i] : 0;
    if (i < N_NODES) g_count[i] = 0;
    int s = v;
#pragma unroll
    for (int o = 1; o < 32; o <<= 1) {
        int t = __shfl_up_sync(0xffffffffu, s, o);
        if ((tid & 31) >= o) s += t;
    }
    if ((tid & 31) == 31) wsum[tid >> 5] = s;
    __syncthreads();
    if (tid < 32) {
        int w = wsum[tid];
        int ws = w;
#pragma unroll
        for (int o = 1; o < 32; o <<= 1) {
            int t = __shfl_up_sync(0xffffffffu, ws, o);
            if (tid >= o) ws += t;
        }
        wsum[tid] = ws - w;
    }
    __syncthreads();
    int excl = s - v + wsum[tid >> 5];
    if (tid == 1023) s_total = excl + v;
    if (tid == 0) s_prefix = 0;
    __syncthreads();

    if (tid == 0) {
        u64 st = ((u64)s_total << 2) | (b == 0 ? 2ull : 1ull);
        atomicExch(&g_state[b], st);
        if (b == 0) g_rowptr[N_NODES] = N_EDGES;
    }
    if (b > 0 && tid < 32) {
        int run = 0, offset = 0;
        while (true) {
            int j = b - 1 - offset - tid;
            u64 st;
            if (j >= 0) {
                do { st = *(volatile u64*)&g_state[j]; } while ((st & 3ull) == 0ull);
            } else st = 2ull;
            unsigned pf = __ballot_sync(0xffffffffu, (st & 3ull) == 2ull);
            int contrib = (int)(st >> 2);
            if (pf) {
                int first = __ffs(pf) - 1;
                if (tid > first) contrib = 0;
#pragma unroll
                for (int o = 16; o; o >>= 1) contrib += __shfl_xor_sync(0xffffffffu, contrib, o);
                run += contrib;
                break;
            } else {
#pragma unroll
                for (int o = 16; o; o >>= 1) contrib += __shfl_xor_sync(0xffffffffu, contrib, o);
                run += contrib;
                offset += 32;
            }
        }
        if (tid == 0) {
            s_prefix = run;
            atomicExch(&g_state[b], (((u64)(run + s_total)) << 2) | 2ull);
        }
    }
    __syncthreads();
    if (i < N_NODES) {
        int val = excl + s_prefix;
        g_rowptr[i] = val;
        g_cursor[i] = val;
    }
}

__global__ void k_scatter(const int* __restrict__ src, const int* __restrict__ dst,
                          const float* __restrict__ kw) {
    int e = blockIdx.x * blockDim.x + threadIdx.x;
    if (e < N_EDGES) {
        int t = dst[e];
        int p = atomicAdd(&g_cursor[t], 1);
        float4 v;
        v.x = __int_as_float(src[e]);
        v.y = kw[e];
        v.z = kw[N_EDGES + e];
        v.w = 0.f;
        g_sedge[p] = v;
    }
}

// ---------------- fused conv0 + mlp0 + L2norm: warp per node; h stored fp16 ----------------
__global__ void k_conv0(const float* __restrict__ x,
                        const float* __restrict__ W0, const float* __restrict__ b0) {
    __shared__ float W0s[512];
    __shared__ float b0s[32];
    int tid = threadIdx.x;
    W0s[tid] = W0[tid];
    W0s[tid + 256] = W0[tid + 256];
    if (tid < 32) b0s[tid] = b0[tid];
    __syncthreads();

    int warp = tid >> 5, lane = tid & 31;
    int node = blockIdx.x * 8 + warp;
    int f = lane & 7, sub = lane >> 3;
    int start = g_rowptr[node], end = g_rowptr[node + 1];
    float a0 = 0.f, a1 = 0.f;
    int e = start;
    for (; e + 4 <= end; e += 4) {
        float4 E = g_sedge[e + sub];
        int s = __float_as_int(E.x);
        float v = __ldg(&x[s * 8 + f]);
        a0 = fmaf(E.y, v, a0);
        a1 = fmaf(E.z, v, a1);
    }
    if (e + sub < end) {
        float4 E = g_sedge[e + sub];
        int s = __float_as_int(E.x);
        float v = __ldg(&x[s * 8 + f]);
        a0 = fmaf(E.y, v, a0);
        a1 = fmaf(E.z, v, a1);
    }
    a0 += __shfl_xor_sync(0xffffffffu, a0, 8);
    a0 += __shfl_xor_sync(0xffffffffu, a0, 16);
    a1 += __shfl_xor_sync(0xffffffffu, a1, 8);
    a1 += __shfl_xor_sync(0xffffffffu, a1, 16);

    float val = (lane & 8) ? a1 : a0;
    float acc = b0s[lane];
#pragma unroll
    for (int k = 0; k < 16; k++) {
        float ak = __shfl_sync(0xffffffffu, val, k);
        acc = fmaf(ak, W0s[k * 32 + lane], acc);
    }
    float ss = acc * acc;
#pragma unroll
    for (int o = 16; o; o >>= 1) ss += __shfl_xor_sync(0xffffffffu, ss, o);
    float sc = 1.f / fmaxf(sqrtf(ss), 1e-12f);
    float hv = acc * sc;
    float hn = __shfl_xor_sync(0xffffffffu, hv, 1);   // neighbor feature
    if ((lane & 1) == 0)
        g_h2[node * 16 + (lane >> 1)] = __floats2half2_rn(hv, hn);
}

// ---------------- layer 1 conv: half-warp per edge (2 edges/gather), fp16 h ----------------
__global__ void k_conv1() {
    int warp = threadIdx.x >> 5, lane = threadIdx.x & 31;
    int node = blockIdx.x * 8 + warp;
    int start = g_rowptr[node], end = g_rowptr[node + 1];
    int fp = lane & 15;        // feature-pair index: features 2fp, 2fp+1
    int sub = lane >> 4;       // which edge of the pair this half-warp handles
    u64 a0 = 0ull, a1 = 0ull;  // packed {feat 2fp, 2fp+1} accum for kernel0/kernel1
    const __half2* __restrict__ h2 = g_h2;

    int e = start;
    for (; e + 4 <= end; e += 4) {
#pragma unroll
        for (int p = 0; p < 2; p++) {
            float4 E = g_sedge[e + 2 * p + sub];
            int s = __float_as_int(E.x);
            float2 v = __half22float2(__ldg(&h2[s * 16 + fp]));
            u64 v2 = pack2(v.x, v.y);
            ffma2(a0, splat2(E.y), v2);
            ffma2(a1, splat2(E.z), v2);
        }
    }
    for (; e < end; e += 2) {
        if (e + sub < end) {
            float4 E = g_sedge[e + sub];
            int s = __float_as_int(E.x);
            float2 v = __half22float2(__ldg(&h2[s * 16 + fp]));
            u64 v2 = pack2(v.x, v.y);
            ffma2(a0, splat2(E.y), v2);
            ffma2(a1, splat2(E.z), v2);
        }
    }

    // combine the two half-warps (edge sub-lanes)
    a0 = add2(a0, __shfl_xor_sync(0xffffffffu, a0, 16));
    a1 = add2(a1, __shfl_xor_sync(0xffffffffu, a1, 16));

    // lanes 0-15 store kernel0 features, lanes 16-31 store kernel1 features
    if (lane < 16)
        *(float2*)(g_agg1 + node * 64 + 2 * fp) = make_float2(lo32(a0), hi32(a0));
    else
        *(float2*)(g_agg1 + node * 64 + 32 + 2 * fp) = make_float2(lo32(a1), hi32(a1));
}

// ---------------- layer 1 MLP: register-tiled SGEMM, 8x8 tile/thread ----------------
#define SM_W1 0
#define SM_A  8192
#define SM_W2 16896
#define SM_B1 25088
#define SM_B2 25216
#define SM_TOTAL 25280

__global__ void __launch_bounds__(256, 2)
k_mlp1(const float* __restrict__ W1, const float* __restrict__ b1,
       const float* __restrict__ W2, const float* __restrict__ b2,
       float* __restrict__ out) {
    extern __shared__ float sm[];
    int tid = threadIdx.x;
    int th = tid & 15;
    int tn = tid >> 4;

    for (int i = tid; i < 8192; i += 256) {
        sm[SM_W1 + i] = W1[i];
        sm[SM_W2 + i] = W2[i];
    }
    if (tid < 128) sm[SM_B1 + tid] = b1[tid];
    if (tid < 64)  sm[SM_B2 + tid] = b2[tid];

    int base = blockIdx.x * 128;
    for (int idx = tid; idx < 8192; idx += 256) {
        int g = base * 64 + idx;
        float v = (g < N_NODES * 64) ? g_agg1[g] : 0.f;
        sm[SM_A + (idx & 63) * 132 + (idx >> 6)] = v;
    }
    __syncthreads();

    u64 acc[32];
#pragma unroll
    for (int i = 0; i < 8; i++) {
        u64 bi = splat2(sm[SM_B1 + th * 8 + i]);
#pragma unroll
        for (int np = 0; np < 4; np++) acc[i * 4 + np] = bi;
    }
    {
        const float* At  = sm + SM_A + tn * 8;
        const float* W1r = sm + SM_W1 + th * 8;
#pragma unroll 4
        for (int k = 0; k < 64; k++) {
            ulonglong2 avA = *(const ulonglong2*)(At + k * 132);
            ulonglong2 avB = *(const ulonglong2*)(At + k * 132 + 4);
            u64 A2[4] = {avA.x, avA.y, avB.x, avB.y};
            float4 w0 = *(const float4*)(W1r + k * 128);
            float4 w1 = *(const float4*)(W1r + k * 128 + 4);
            u64 ws[8] = {splat2(w0.x), splat2(w0.y), splat2(w0.z), splat2(w0.w),
                         splat2(w1.x), splat2(w1.y), splat2(w1.z), splat2(w1.w)};
#pragma unroll
            for (int i = 0; i < 8; i++)
#pragma unroll
                for (int np = 0; np < 4; np++)
                    ffma2(acc[i * 4 + np], A2[np], ws[i]);
        }
    }
    __syncthreads();

    {
        float* Zs = sm;
#pragma unroll
        for (int i = 0; i < 8; i++) {
            int hh = th * 8 + i;
            int rot = hh >> 3;
            float* row = Zs + hh * 132;
#pragma unroll
            for (int np = 0; np < 4; np++) {
                u64 v = acc[i * 4 + np];
                u64 r = pack2(fmaxf(lo32(v), 0.f), fmaxf(hi32(v), 0.f));
                int q  = 2 * tn + (np >> 1);
                int qp = (q + rot) & 31;
                *(u64*)(row + qp * 4 + (np & 1) * 2) = r;
            }
        }
    }
    __syncthreads();

    u64 acc2[16];
#pragma unroll
    for (int o = 0; o < 4; o++) {
        u64 bo = splat2(sm[SM_B2 + th * 4 + o]);
#pragma unroll
        for (int np = 0; np < 4; np++) acc2[o * 4 + np] = bo;
    }
    {
        const float* Zs  = sm;
        const float* W2r = sm + SM_W2 + th * 4;
#pragma unroll 4
        for (int k = 0; k < 128; k++) {
            int rot = k >> 3;
            const float* row = Zs + k * 132;
            ulonglong2 z0 = *(const ulonglong2*)(row + (((2 * tn + 0 + rot) & 31) << 2));
            ulonglong2 z1 = *(const ulonglong2*)(row + (((2 * tn + 1 + rot) & 31) << 2));
            u64 A2[4] = {z0.x, z0.y, z1.x, z1.y};
            float4 wv = *(const float4*)(W2r + k * 64);
            u64 ws[4] = {splat2(wv.x), splat2(wv.y), splat2(wv.z), splat2(wv.w)};
#pragma unroll
            for (int o = 0; o < 4; o++)
#pragma unroll
                for (int np = 0; np < 4; np++)
                    ffma2(acc2[o * 4 + np], A2[np], ws[o]);
        }
    }

    u64 ss2[4];
#pragma unroll
    for (int np = 0; np < 4; np++) ss2[np] = 0ull;
#pragma unroll
    for (int o = 0; o < 4; o++)
#pragma unroll
        for (int np = 0; np < 4; np++)
            ffma2(ss2[np], acc2[o * 4 + np], acc2[o * 4 + np]);
#pragma unroll
    for (int m = 1; m < 16; m <<= 1)
#pragma unroll
        for (int np = 0; np < 4; np++)
            ss2[np] = add2(ss2[np], __shfl_xor_sync(0xffffffffu, ss2[np], m));

#pragma unroll
    for (int np = 0; np < 4; np++) {
        float se = 1.f / fmaxf(sqrtf(lo32(ss2[np])), 1e-12f);
        float so = 1.f / fmaxf(sqrtf(hi32(ss2[np])), 1e-12f);
        int ne = base + tn * 8 + 2 * np;
        if (ne < N_NODES) {
            float4 v;
            v.x = lo32(acc2[0 * 4 + np]) * se;
            v.y = lo32(acc2[1 * 4 + np]) * se;
            v.z = lo32(acc2[2 * 4 + np]) * se;
            v.w = lo32(acc2[3 * 4 + np]) * se;
            *(float4*)(out + ne * 64 + th * 4) = v;
        }
        if (ne + 1 < N_NODES) {
            float4 v;
            v.x = hi32(acc2[0 * 4 + np]) * so;
            v.y = hi32(acc2[1 * 4 + np]) * so;
            v.z = hi32(acc2[2 * 4 + np]) * so;
            v.w = hi32(acc2[3 * 4 + np]) * so;
            *(float4*)(out + (ne + 1) * 64 + th * 4) = v;
        }
    }
}

// ---------------- launch ----------------
extern "C" void kernel_launch(void* const* d_in, const int* in_sizes, int n_in,
                              void* d_out, int out_size) {
    const float* x  = (const float*)d_in[0];
    const int*   ei = (const int*)  d_in[1];
    const float* kw = (const float*)d_in[2];
    const float* W0 = (const float*)d_in[3];
    const float* b0 = (const float*)d_in[4];
    const float* W1 = (const float*)d_in[5];
    const float* b1 = (const float*)d_in[6];
    const float* W2 = (const float*)d_in[7];
    const float* b2 = (const float*)d_in[8];
    float* out = (float*)d_out;
    const int* src = ei;
    const int* dst = ei + N_EDGES;

    cudaFuncSetAttribute(k_mlp1, cudaFuncAttributeMaxDynamicSharedMemorySize,
                         SM_TOTAL * (int)sizeof(float));

    k_hist   <<<(N_EDGES + 255) / 256, 256>>>(dst);              // launch 0
    k_scan   <<<(N_NODES + 1023) / 1024, 1024>>>();              // launch 1
    k_scatter<<<(N_EDGES + 255) / 256, 256>>>(src, dst, kw);     // launch 2
    k_conv0  <<<N_NODES / 8, 256>>>(x, W0, b0);                  // launch 3 (ncu window)
    k_conv1  <<<N_NODES / 8, 256>>>();                           // launch 4
    k_mlp1   <<<(N_NODES + 127) / 128, 256, SM_TOTAL * (int)sizeof(float)>>>(W1, b1, W2, b2, out);
}

// round 10
// speedup vs baseline: 1.1192x; 1.0104x over previous
#include <cuda_runtime.h>
#include <math.h>

#define N_NODES 200000
#define N_EDGES 3200000

typedef unsigned long long u64;

// ---------------- static scratch ----------------
__device__ int      g_count [N_NODES];
__device__ int      g_rowptr[N_NODES + 1];
__device__ int      g_cursor[N_NODES];
__device__ u64      g_state [256];        // decoupled-lookback: (sum<<2)|flag
__device__ float4   g_sedge [N_EDGES];    // {src(bits), kw0, kw1, pad}
__device__ float    g_h     [N_NODES * 32];
__device__ float    g_agg1  [N_NODES * 64];

// ---------------- packed f32x2 helpers ----------------
__device__ __forceinline__ u64 splat2(float x) {
    u64 r; unsigned xi = __float_as_uint(x);
    asm("mov.b64 %0, {%1, %1};" : "=l"(r) : "r"(xi));
    return r;
}
__device__ __forceinline__ void ffma2(u64& d, u64 a, u64 b) {
    asm("fma.rn.f32x2 %0, %1, %2, %0;" : "+l"(d) : "l"(a), "l"(b));
}
__device__ __forceinline__ u64 add2(u64 a, u64 b) {
    u64 r; asm("add.rn.f32x2 %0, %1, %2;" : "=l"(r) : "l"(a), "l"(b));
    return r;
}
__device__ __forceinline__ float lo32(u64 v) { return __uint_as_float((unsigned)v); }
__device__ __forceinline__ float hi32(u64 v) { return __uint_as_float((unsigned)(v >> 32)); }
__device__ __forceinline__ u64 pack2(float lo, float hi) {
    return ((u64)__float_as_uint(hi) << 32) | (u64)__float_as_uint(lo);
}

// ---------------- CSR build ----------------
__global__ void k_hist(const int* __restrict__ dst) {
    int tid = threadIdx.x;
    if (blockIdx.x == 0 && tid < 256) g_state[tid] = 0ull;
    int e = blockIdx.x * blockDim.x + tid;
    if (e < N_EDGES) atomicAdd(&g_count[dst[e]], 1);
}

__global__ void __launch_bounds__(1024, 2) k_scan() {
    __shared__ int wsum[32];
    __shared__ int s_total;
    __shared__ int s_prefix;
    int tid = threadIdx.x, b = blockIdx.x;
    int i = b * 1024 + tid;
    int v = (i < N_NODES) ? g_count[i] : 0;
    if (i < N_NODES) g_count[i] = 0;
    int s = v;
#pragma unroll
    for (int o = 1; o < 32; o <<= 1) {
        int t = __shfl_up_sync(0xffffffffu, s, o);
        if ((tid & 31) >= o) s += t;
    }
    if ((tid & 31) == 31) wsum[tid >> 5] = s;
    __syncthreads();
    if (tid < 32) {
        int w = wsum[tid];
        int ws = w;
#pragma unroll
        for (int o = 1; o < 32; o <<= 1) {
            int t = __shfl_up_sync(0xffffffffu, ws, o);
            if (tid >= o) ws += t;
        }
        wsum[tid] = ws - w;
    }
    __syncthreads();
    int excl = s - v + wsum[tid >> 5];
    if (tid == 1023) s_total = excl + v;
    if (tid == 0) s_prefix = 0;
    __syncthreads();

    if (tid == 0) {
        u64 st = ((u64)s_total << 2) | (b == 0 ? 2ull : 1ull);
        atomicExch(&g_state[b], st);
        if (b == 0) g_rowptr[N_NODES] = N_EDGES;
    }
    if (b > 0 && tid < 32) {
        int run = 0, offset = 0;
        while (true) {
            int j = b - 1 - offset - tid;
            u64 st;
            if (j >= 0) {
                do { st = *(volatile u64*)&g_state[j]; } while ((st & 3ull) == 0ull);
            } else st = 2ull;
            unsigned pf = __ballot_sync(0xffffffffu, (st & 3ull) == 2ull);
            int contrib = (int)(st >> 2);
            if (pf) {
                int first = __ffs(pf) - 1;
                if (tid > first) contrib = 0;
#pragma unroll
                for (int o = 16; o; o >>= 1) contrib += __shfl_xor_sync(0xffffffffu, contrib, o);
                run += contrib;
                break;
            } else {
#pragma unroll
                for (int o = 16; o; o >>= 1) contrib += __shfl_xor_sync(0xffffffffu, contrib, o);
                run += contrib;
                offset += 32;
            }
        }
        if (tid == 0) {
            s_prefix = run;
            atomicExch(&g_state[b], (((u64)(run + s_total)) << 2) | 2ull);
        }
    }
    __syncthreads();
    if (i < N_NODES) {
        int val = excl + s_prefix;
        g_rowptr[i] = val;
        g_cursor[i] = val;
    }
}

__global__ void k_scatter(const int* __restrict__ src, const int* __restrict__ dst,
                          const float* __restrict__ kw) {
    int e = blockIdx.x * blockDim.x + threadIdx.x;
    if (e < N_EDGES) {
        int t = dst[e];
        int p = atomicAdd(&g_cursor[t], 1);
        float4 v;
        v.x = __int_as_float(src[e]);
        v.y = kw[e];
        v.z = kw[N_EDGES + e];
        v.w = 0.f;
        g_sedge[p] = v;
    }
}

// ---------------- fused conv0 + mlp0 + L2norm: warp per node, 8-edge batch ----------------
__global__ void k_conv0(const float* __restrict__ x,
                        const float* __restrict__ W0, const float* __restrict__ b0) {
    __shared__ float W0s[512];
    __shared__ float b0s[32];
    int tid = threadIdx.x;
    W0s[tid] = W0[tid];
    W0s[tid + 256] = W0[tid + 256];
    if (tid < 32) b0s[tid] = b0[tid];
    __syncthreads();

    int warp = tid >> 5, lane = tid & 31;
    int node = blockIdx.x * 8 + warp;
    int f = lane & 7, sub = lane >> 3;
    int start = g_rowptr[node], end = g_rowptr[node + 1];
    float a0 = 0.f, a1 = 0.f;
    int e = start;
    for (; e + 8 <= end; e += 8) {           // 8 edges per warp-iter, 2 per lane
        float4 Ea = g_sedge[e + sub];
        float4 Eb = g_sedge[e + 4 + sub];
        float va = __ldg(&x[__float_as_int(Ea.x) * 8 + f]);
        float vb = __ldg(&x[__float_as_int(Eb.x) * 8 + f]);
        a0 = fmaf(Ea.y, va, a0); a1 = fmaf(Ea.z, va, a1);
        a0 = fmaf(Eb.y, vb, a0); a1 = fmaf(Eb.z, vb, a1);
    }
    for (; e + 4 <= end; e += 4) {
        float4 E = g_sedge[e + sub];
        float v = __ldg(&x[__float_as_int(E.x) * 8 + f]);
        a0 = fmaf(E.y, v, a0);
        a1 = fmaf(E.z, v, a1);
    }
    if (e + sub < end) {
        float4 E = g_sedge[e + sub];
        float v = __ldg(&x[__float_as_int(E.x) * 8 + f]);
        a0 = fmaf(E.y, v, a0);
        a1 = fmaf(E.z, v, a1);
    }
    a0 += __shfl_xor_sync(0xffffffffu, a0, 8);
    a0 += __shfl_xor_sync(0xffffffffu, a0, 16);
    a1 += __shfl_xor_sync(0xffffffffu, a1, 8);
    a1 += __shfl_xor_sync(0xffffffffu, a1, 16);

    float val = (lane & 8) ? a1 : a0;
    float acc = b0s[lane];
#pragma unroll
    for (int k = 0; k < 16; k++) {
        float ak = __shfl_sync(0xffffffffu, val, k);
        acc = fmaf(ak, W0s[k * 32 + lane], acc);
    }
    float ss = acc * acc;
#pragma unroll
    for (int o = 16; o; o >>= 1) ss += __shfl_xor_sync(0xffffffffu, ss, o);
    float sc = 1.f / fmaxf(sqrtf(ss), 1e-12f);
    g_h[node * 32 + lane] = acc * sc;
}

// ---------------- layer 1 conv: warp per node, lane = feature, 8-edge batch ----------------
__global__ void k_conv1() {
    int warp = threadIdx.x >> 5, lane = threadIdx.x & 31;
    int node = blockIdx.x * 8 + warp;
    int start = g_rowptr[node], end = g_rowptr[node + 1];
    float a0 = 0.f, a1 = 0.f;
    const float* __restrict__ h = g_h;
    int e = start;
    for (; e + 8 <= end; e += 8) {
        float4 E0 = g_sedge[e],   E1 = g_sedge[e+1], E2 = g_sedge[e+2], E3 = g_sedge[e+3];
        float4 E4 = g_sedge[e+4], E5 = g_sedge[e+5], E6 = g_sedge[e+6], E7 = g_sedge[e+7];
        float v0 = h[__float_as_int(E0.x) * 32 + lane];
        float v1 = h[__float_as_int(E1.x) * 32 + lane];
        float v2 = h[__float_as_int(E2.x) * 32 + lane];
        float v3 = h[__float_as_int(E3.x) * 32 + lane];
        float v4 = h[__float_as_int(E4.x) * 32 + lane];
        float v5 = h[__float_as_int(E5.x) * 32 + lane];
        float v6 = h[__float_as_int(E6.x) * 32 + lane];
        float v7 = h[__float_as_int(E7.x) * 32 + lane];
        a0 = fmaf(E0.y, v0, a0); a1 = fmaf(E0.z, v0, a1);
        a0 = fmaf(E1.y, v1, a0); a1 = fmaf(E1.z, v1, a1);
        a0 = fmaf(E2.y, v2, a0); a1 = fmaf(E2.z, v2, a1);
        a0 = fmaf(E3.y, v3, a0); a1 = fmaf(E3.z, v3, a1);
        a0 = fmaf(E4.y, v4, a0); a1 = fmaf(E4.z, v4, a1);
        a0 = fmaf(E5.y, v5, a0); a1 = fmaf(E5.z, v5, a1);
        a0 = fmaf(E6.y, v6, a0); a1 = fmaf(E6.z, v6, a1);
        a0 = fmaf(E7.y, v7, a0); a1 = fmaf(E7.z, v7, a1);
    }
    for (; e + 4 <= end; e += 4) {
        float4 E0 = g_sedge[e], E1 = g_sedge[e+1], E2 = g_sedge[e+2], E3 = g_sedge[e+3];
        float v0 = h[__float_as_int(E0.x) * 32 + lane];
        float v1 = h[__float_as_int(E1.x) * 32 + lane];
        float v2 = h[__float_as_int(E2.x) * 32 + lane];
        float v3 = h[__float_as_int(E3.x) * 32 + lane];
        a0 = fmaf(E0.y, v0, a0); a1 = fmaf(E0.z, v0, a1);
        a0 = fmaf(E1.y, v1, a0); a1 = fmaf(E1.z, v1, a1);
        a0 = fmaf(E2.y, v2, a0); a1 = fmaf(E2.z, v2, a1);
        a0 = fmaf(E3.y, v3, a0); a1 = fmaf(E3.z, v3, a1);
    }
    for (; e < end; ++e) {
        float4 E = g_sedge[e];
        float v = h[__float_as_int(E.x) * 32 + lane];
        a0 = fmaf(E.y, v, a0);
        a1 = fmaf(E.z, v, a1);
    }
    g_agg1[node*64 + lane]      = a0;
    g_agg1[node*64 + 32 + lane] = a1;
}

// ---------------- layer 1 MLP: register-tiled SGEMM, 8x8 tile/thread ----------------
#define SM_W1 0
#define SM_A  8192
#define SM_W2 16896
#define SM_B1 25088
#define SM_B2 25216
#define SM_TOTAL 25280

__global__ void __launch_bounds__(256, 2)
k_mlp1(const float* __restrict__ W1, const float* __restrict__ b1,
       const float* __restrict__ W2, const float* __restrict__ b2,
       float* __restrict__ out) {
    extern __shared__ float sm[];
    int tid = threadIdx.x;
    int th = tid & 15;
    int tn = tid >> 4;

    for (int i = tid; i < 8192; i += 256) {
        sm[SM_W1 + i] = W1[i];
        sm[SM_W2 + i] = W2[i];
    }
    if (tid < 128) sm[SM_B1 + tid] = b1[tid];
    if (tid < 64)  sm[SM_B2 + tid] = b2[tid];

    int base = blockIdx.x * 128;
    for (int idx = tid; idx < 8192; idx += 256) {
        int g = base * 64 + idx;
        float v = (g < N_NODES * 64) ? g_agg1[g] : 0.f;
        sm[SM_A + (idx & 63) * 132 + (idx >> 6)] = v;
    }
    __syncthreads();

    u64 acc[32];
#pragma unroll
    for (int i = 0; i < 8; i++) {
        u64 bi = splat2(sm[SM_B1 + th * 8 + i]);
#pragma unroll
        for (int np = 0; np < 4; np++) acc[i * 4 + np] = bi;
    }
    {
        const float* At  = sm + SM_A + tn * 8;
        const float* W1r = sm + SM_W1 + th * 8;
#pragma unroll 4
        for (int k = 0; k < 64; k++) {
            ulonglong2 avA = *(const ulonglong2*)(At + k * 132);
            ulonglong2 avB = *(const ulonglong2*)(At + k * 132 + 4);
            u64 A2[4] = {avA.x, avA.y, avB.x, avB.y};
            float4 w0 = *(const float4*)(W1r + k * 128);
            float4 w1 = *(const float4*)(W1r + k * 128 + 4);
            u64 ws[8] = {splat2(w0.x), splat2(w0.y), splat2(w0.z), splat2(w0.w),
                         splat2(w1.x), splat2(w1.y), splat2(w1.z), splat2(w1.w)};
#pragma unroll
            for (int i = 0; i < 8; i++)
#pragma unroll
                for (int np = 0; np < 4; np++)
                    ffma2(acc[i * 4 + np], A2[np], ws[i]);
        }
    }
    __syncthreads();

    {
        float* Zs = sm;
#pragma unroll
        for (int i = 0; i < 8; i++) {
            int hh = th * 8 + i;
            int rot = hh >> 3;
            float* row = Zs + hh * 132;
#pragma unroll
            for (int np = 0; np < 4; np++) {
                u64 v = acc[i * 4 + np];
                u64 r = pack2(fmaxf(lo32(v), 0.f), fmaxf(hi32(v), 0.f));
                int q  = 2 * tn + (np >> 1);
                int qp = (q + rot) & 31;
                *(u64*)(row + qp * 4 + (np & 1) * 2) = r;
            }
        }
    }
    __syncthreads();

    u64 acc2[16];
#pragma unroll
    for (int o = 0; o < 4; o++) {
        u64 bo = splat2(sm[SM_B2 + th * 4 + o]);
#pragma unroll
        for (int np = 0; np < 4; np++) acc2[o * 4 + np] = bo;
    }
    {
        const float* Zs  = sm;
        const float* W2r = sm + SM_W2 + th * 4;
#pragma unroll 4
        for (int k = 0; k < 128; k++) {
            int rot = k >> 3;
            const float* row = Zs + k * 132;
            ulonglong2 z0 = *(const ulonglong2*)(row + (((2 * tn + 0 + rot) & 31) << 2));
            ulonglong2 z1 = *(const ulonglong2*)(row + (((2 * tn + 1 + rot) & 31) << 2));
            u64 A2[4] = {z0.x, z0.y, z1.x, z1.y};
            float4 wv = *(const float4*)(W2r + k * 64);
            u64 ws[4] = {splat2(wv.x), splat2(wv.y), splat2(wv.z), splat2(wv.w)};
#pragma unroll
            for (int o = 0; o < 4; o++)
#pragma unroll
                for (int np = 0; np < 4; np++)
                    ffma2(acc2[o * 4 + np], A2[np], ws[o]);
        }
    }

    u64 ss2[4];
#pragma unroll
    for (int np = 0; np < 4; np++) ss2[np] = 0ull;
#pragma unroll
    for (int o = 0; o < 4; o++)
#pragma unroll
        for (int np = 0; np < 4; np++)
            ffma2(ss2[np], acc2[o * 4 + np], acc2[o * 4 + np]);
#pragma unroll
    for (int m = 1; m < 16; m <<= 1)
#pragma unroll
        for (int np = 0; np < 4; np++)
            ss2[np] = add2(ss2[np], __shfl_xor_sync(0xffffffffu, ss2[np], m));

#pragma unroll
    for (int np = 0; np < 4; np++) {
        float se = 1.f / fmaxf(sqrtf(lo32(ss2[np])), 1e-12f);
        float so = 1.f / fmaxf(sqrtf(hi32(ss2[np])), 1e-12f);
        int ne = base + tn * 8 + 2 * np;
        if (ne < N_NODES) {
            float4 v;
            v.x = lo32(acc2[0 * 4 + np]) * se;
            v.y = lo32(acc2[1 * 4 + np]) * se;
            v.z = lo32(acc2[2 * 4 + np]) * se;
            v.w = lo32(acc2[3 * 4 + np]) * se;
            *(float4*)(out + ne * 64 + th * 4) = v;
        }
        if (ne + 1 < N_NODES) {
            float4 v;
            v.x = hi32(acc2[0 * 4 + np]) * so;
            v.y = hi32(acc2[1 * 4 + np]) * so;
            v.z = hi32(acc2[2 * 4 + np]) * so;
            v.w = hi32(acc2[3 * 4 + np]) * so;
            *(float4*)(out + (ne + 1) * 64 + th * 4) = v;
        }
    }
}

// ---------------- launch ----------------
extern "C" void kernel_launch(void* const* d_in, const int* in_sizes, int n_in,
                              void* d_out, int out_size) {
    const float* x  = (const float*)d_in[0];
    const int*   ei = (const int*)  d_in[1];
    const float* kw = (const float*)d_in[2];
    const float* W0 = (const float*)d_in[3];
    const float* b0 = (const float*)d_in[4];
    const float* W1 = (const float*)d_in[5];
    const float* b1 = (const float*)d_in[6];
    const float* W2 = (const float*)d_in[7];
    const float* b2 = (const float*)d_in[8];
    float* out = (float*)d_out;
    const int* src = ei;
    const int* dst = ei + N_EDGES;

    cudaFuncSetAttribute(k_mlp1, cudaFuncAttributeMaxDynamicSharedMemorySize,
                         SM_TOTAL * (int)sizeof(float));

    k_hist   <<<(N_EDGES + 255) / 256, 256>>>(dst);              // launch 0
    k_scan   <<<(N_NODES + 1023) / 1024, 1024>>>();              // launch 1
    k_scatter<<<(N_EDGES + 255) / 256, 256>>>(src, dst, kw);     // launch 2
    k_conv0  <<<N_NODES / 8, 256>>>(x, W0, b0);                  // launch 3 (ncu window)
    k_conv1  <<<N_NODES / 8, 256>>>();                           // launch 4
    k_mlp1   <<<(N_NODES + 127) / 128, 256, SM_TOTAL * (int)sizeof(float)>>>(W1, b1, W2, b2, out);
}

// round 11
// speedup vs baseline: 1.1629x; 1.0390x over previous
#include <cuda_runtime.h>
#include <math.h>

#define N_NODES 200000
#define N_EDGES 3200000

typedef unsigned long long u64;

// ---------------- static scratch ----------------
__device__ int      g_count [N_NODES];
__device__ int      g_rowptr[N_NODES + 1];
__device__ int      g_cursor[N_NODES];
__device__ u64      g_state [256];        // decoupled-lookback: (sum<<2)|flag
__device__ float4   g_sedge [N_EDGES];    // {src(bits), kw0, kw1, pad}
__device__ float    g_h     [N_NODES * 32];
__device__ float    g_agg1  [N_NODES * 64];

// ---------------- packed f32x2 helpers ----------------
__device__ __forceinline__ u64 splat2(float x) {
    u64 r; unsigned xi = __float_as_uint(x);
    asm("mov.b64 %0, {%1, %1};" : "=l"(r) : "r"(xi));
    return r;
}
__device__ __forceinline__ void ffma2(u64& d, u64 a, u64 b) {
    asm("fma.rn.f32x2 %0, %1, %2, %0;" : "+l"(d) : "l"(a), "l"(b));
}
__device__ __forceinline__ u64 add2(u64 a, u64 b) {
    u64 r; asm("add.rn.f32x2 %0, %1, %2;" : "=l"(r) : "l"(a), "l"(b));
    return r;
}
__device__ __forceinline__ float lo32(u64 v) { return __uint_as_float((unsigned)v); }
__device__ __forceinline__ float hi32(u64 v) { return __uint_as_float((unsigned)(v >> 32)); }
__device__ __forceinline__ u64 pack2(float lo, float hi) {
    return ((u64)__float_as_uint(hi) << 32) | (u64)__float_as_uint(lo);
}

// ---------------- CSR build ----------------
__global__ void k_hist(const int* __restrict__ dst) {
    int tid = threadIdx.x;
    if (blockIdx.x == 0 && tid < 256) g_state[tid] = 0ull;
    int e = blockIdx.x * blockDim.x + tid;
    if (e < N_EDGES) atomicAdd(&g_count[dst[e]], 1);
}

__global__ void __launch_bounds__(1024, 2) k_scan() {
    __shared__ int wsum[32];
    __shared__ int s_total;
    __shared__ int s_prefix;
    int tid = threadIdx.x, b = blockIdx.x;
    int i = b * 1024 + tid;
    int v = (i < N_NODES) ? g_count[i] : 0;
    if (i < N_NODES) g_count[i] = 0;
    int s = v;
#pragma unroll
    for (int o = 1; o < 32; o <<= 1) {
        int t = __shfl_up_sync(0xffffffffu, s, o);
        if ((tid & 31) >= o) s += t;
    }
    if ((tid & 31) == 31) wsum[tid >> 5] = s;
    __syncthreads();
    if (tid < 32) {
        int w = wsum[tid];
        int ws = w;
#pragma unroll
        for (int o = 1; o < 32; o <<= 1) {
            int t = __shfl_up_sync(0xffffffffu, ws, o);
            if (tid >= o) ws += t;
        }
        wsum[tid] = ws - w;
    }
    __syncthreads();
    int excl = s - v + wsum[tid >> 5];
    if (tid == 1023) s_total = excl + v;
    if (tid == 0) s_prefix = 0;
    __syncthreads();

    if (tid == 0) {
        u64 st = ((u64)s_total << 2) | (b == 0 ? 2ull : 1ull);
        atomicExch(&g_state[b], st);
        if (b == 0) g_rowptr[N_NODES] = N_EDGES;
    }
    if (b > 0 && tid < 32) {
        int run = 0, offset = 0;
        while (true) {
            int j = b - 1 - offset - tid;
            u64 st;
            if (j >= 0) {
                do { st = *(volatile u64*)&g_state[j]; } while ((st & 3ull) == 0ull);
            } else st = 2ull;
            unsigned pf = __ballot_sync(0xffffffffu, (st & 3ull) == 2ull);
            int contrib = (int)(st >> 2);
            if (pf) {
                int first = __ffs(pf) - 1;
                if (tid > first) contrib = 0;
#pragma unroll
                for (int o = 16; o; o >>= 1) contrib += __shfl_xor_sync(0xffffffffu, contrib, o);
                run += contrib;
                break;
            } else {
#pragma unroll
                for (int o = 16; o; o >>= 1) contrib += __shfl_xor_sync(0xffffffffu, contrib, o);
                run += contrib;
                offset += 32;
            }
        }
        if (tid == 0) {
            s_prefix = run;
            atomicExch(&g_state[b], (((u64)(run + s_total)) << 2) | 2ull);
        }
    }
    __syncthreads();
    if (i < N_NODES) {
        int val = excl + s_prefix;
        g_rowptr[i] = val;
        g_cursor[i] = val;
    }
}

__global__ void k_scatter(const int* __restrict__ src, const int* __restrict__ dst,
                          const float* __restrict__ kw) {
    int e = blockIdx.x * blockDim.x + threadIdx.x;
    if (e < N_EDGES) {
        int t = dst[e];
        int p = atomicAdd(&g_cursor[t], 1);
        float4 v;
        v.x = __int_as_float(src[e]);
        v.y = kw[e];
        v.z = kw[N_EDGES + e];
        v.w = 0.f;
        g_sedge[p] = v;
    }
}

// ---------------- fused conv0 + mlp0 + L2norm: 8 nodes per warp (imbalance averaging) ----------------
__global__ void k_conv0(const float* __restrict__ x,
                        const float* __restrict__ W0, const float* __restrict__ b0) {
    __shared__ float W0s[512];
    __shared__ float b0s[32];
    int tid = threadIdx.x;
    W0s[tid] = W0[tid];
    W0s[tid + 256] = W0[tid + 256];
    if (tid < 32) b0s[tid] = b0[tid];
    __syncthreads();

    int warp = tid >> 5, lane = tid & 31;
    int nodeBase = (blockIdx.x * 8 + warp) * 8;
    int f = lane & 7, sub = lane >> 3;

#pragma unroll 1
    for (int n = 0; n < 8; n++) {
        int node = nodeBase + n;
        int start = g_rowptr[node], end = g_rowptr[node + 1];
        float a0 = 0.f, a1 = 0.f;
        int e = start;
        for (; e + 8 <= end; e += 8) {
            float4 Ea = g_sedge[e + sub];
            float4 Eb = g_sedge[e + 4 + sub];
            float va = __ldg(&x[__float_as_int(Ea.x) * 8 + f]);
            float vb = __ldg(&x[__float_as_int(Eb.x) * 8 + f]);
            a0 = fmaf(Ea.y, va, a0); a1 = fmaf(Ea.z, va, a1);
            a0 = fmaf(Eb.y, vb, a0); a1 = fmaf(Eb.z, vb, a1);
        }
        for (; e + 4 <= end; e += 4) {
            float4 E = g_sedge[e + sub];
            float v = __ldg(&x[__float_as_int(E.x) * 8 + f]);
            a0 = fmaf(E.y, v, a0);
            a1 = fmaf(E.z, v, a1);
        }
        if (e + sub < end) {
            float4 E = g_sedge[e + sub];
            float v = __ldg(&x[__float_as_int(E.x) * 8 + f]);
            a0 = fmaf(E.y, v, a0);
            a1 = fmaf(E.z, v, a1);
        }
        a0 += __shfl_xor_sync(0xffffffffu, a0, 8);
        a0 += __shfl_xor_sync(0xffffffffu, a0, 16);
        a1 += __shfl_xor_sync(0xffffffffu, a1, 8);
        a1 += __shfl_xor_sync(0xffffffffu, a1, 16);

        float val = (lane & 8) ? a1 : a0;
        float acc = b0s[lane];
#pragma unroll
        for (int k = 0; k < 16; k++) {
            float ak = __shfl_sync(0xffffffffu, val, k);
            acc = fmaf(ak, W0s[k * 32 + lane], acc);
        }
        float ss = acc * acc;
#pragma unroll
        for (int o = 16; o; o >>= 1) ss += __shfl_xor_sync(0xffffffffu, ss, o);
        float sc = 1.f / fmaxf(sqrtf(ss), 1e-12f);
        g_h[node * 32 + lane] = acc * sc;
    }
}

// ---------------- layer 1 conv: 8 nodes per warp, lane = feature ----------------
__global__ void k_conv1() {
    int warp = threadIdx.x >> 5, lane = threadIdx.x & 31;
    int nodeBase = (blockIdx.x * 8 + warp) * 8;
    const float* __restrict__ h = g_h;

#pragma unroll 1
    for (int n = 0; n < 8; n++) {
        int node = nodeBase + n;
        int start = g_rowptr[node], end = g_rowptr[node + 1];
        float a0 = 0.f, a1 = 0.f;
        int e = start;
        for (; e + 8 <= end; e += 8) {
            float4 E0 = g_sedge[e],   E1 = g_sedge[e+1], E2 = g_sedge[e+2], E3 = g_sedge[e+3];
            float4 E4 = g_sedge[e+4], E5 = g_sedge[e+5], E6 = g_sedge[e+6], E7 = g_sedge[e+7];
            float v0 = h[__float_as_int(E0.x) * 32 + lane];
            float v1 = h[__float_as_int(E1.x) * 32 + lane];
            float v2 = h[__float_as_int(E2.x) * 32 + lane];
            float v3 = h[__float_as_int(E3.x) * 32 + lane];
            float v4 = h[__float_as_int(E4.x) * 32 + lane];
            float v5 = h[__float_as_int(E5.x) * 32 + lane];
            float v6 = h[__float_as_int(E6.x) * 32 + lane];
            float v7 = h[__float_as_int(E7.x) * 32 + lane];
            a0 = fmaf(E0.y, v0, a0); a1 = fmaf(E0.z, v0, a1);
            a0 = fmaf(E1.y, v1, a0); a1 = fmaf(E1.z, v1, a1);
            a0 = fmaf(E2.y, v2, a0); a1 = fmaf(E2.z, v2, a1);
            a0 = fmaf(E3.y, v3, a0); a1 = fmaf(E3.z, v3, a1);
            a0 = fmaf(E4.y, v4, a0); a1 = fmaf(E4.z, v4, a1);
            a0 = fmaf(E5.y, v5, a0); a1 = fmaf(E5.z, v5, a1);
            a0 = fmaf(E6.y, v6, a0); a1 = fmaf(E6.z, v6, a1);
            a0 = fmaf(E7.y, v7, a0); a1 = fmaf(E7.z, v7, a1);
        }
        for (; e + 4 <= end; e += 4) {
            float4 E0 = g_sedge[e], E1 = g_sedge[e+1], E2 = g_sedge[e+2], E3 = g_sedge[e+3];
            float v0 = h[__float_as_int(E0.x) * 32 + lane];
            float v1 = h[__float_as_int(E1.x) * 32 + lane];
            float v2 = h[__float_as_int(E2.x) * 32 + lane];
            float v3 = h[__float_as_int(E3.x) * 32 + lane];
            a0 = fmaf(E0.y, v0, a0); a1 = fmaf(E0.z, v0, a1);
            a0 = fmaf(E1.y, v1, a0); a1 = fmaf(E1.z, v1, a1);
            a0 = fmaf(E2.y, v2, a0); a1 = fmaf(E2.z, v2, a1);
            a0 = fmaf(E3.y, v3, a0); a1 = fmaf(E3.z, v3, a1);
        }
        for (; e < end; ++e) {
            float4 E = g_sedge[e];
            float v = h[__float_as_int(E.x) * 32 + lane];
            a0 = fmaf(E.y, v, a0);
            a1 = fmaf(E.z, v, a1);
        }
        g_agg1[node*64 + lane]      = a0;
        g_agg1[node*64 + 32 + lane] = a1;
    }
}

// ---------------- layer 1 MLP: register-tiled SGEMM, 8x8 tile/thread ----------------
#define SM_W1 0
#define SM_A  8192
#define SM_W2 16896
#define SM_B1 25088
#define SM_B2 25216
#define SM_TOTAL 25280

__global__ void __launch_bounds__(256, 2)
k_mlp1(const float* __restrict__ W1, const float* __restrict__ b1,
       const float* __restrict__ W2, const float* __restrict__ b2,
       float* __restrict__ out) {
    extern __shared__ float sm[];
    int tid = threadIdx.x;
    int th = tid & 15;
    int tn = tid >> 4;

    for (int i = tid; i < 8192; i += 256) {
        sm[SM_W1 + i] = W1[i];
        sm[SM_W2 + i] = W2[i];
    }
    if (tid < 128) sm[SM_B1 + tid] = b1[tid];
    if (tid < 64)  sm[SM_B2 + tid] = b2[tid];

    int base = blockIdx.x * 128;
    for (int idx = tid; idx < 8192; idx += 256) {
        int g = base * 64 + idx;
        float v = (g < N_NODES * 64) ? g_agg1[g] : 0.f;
        sm[SM_A + (idx & 63) * 132 + (idx >> 6)] = v;
    }
    __syncthreads();

    u64 acc[32];
#pragma unroll
    for (int i = 0; i < 8; i++) {
        u64 bi = splat2(sm[SM_B1 + th * 8 + i]);
#pragma unroll
        for (int np = 0; np < 4; np++) acc[i * 4 + np] = bi;
    }
    {
        const float* At  = sm + SM_A + tn * 8;
        const float* W1r = sm + SM_W1 + th * 8;
#pragma unroll 4
        for (int k = 0; k < 64; k++) {
            ulonglong2 avA = *(const ulonglong2*)(At + k * 132);
            ulonglong2 avB = *(const ulonglong2*)(At + k * 132 + 4);
            u64 A2[4] = {avA.x, avA.y, avB.x, avB.y};
            float4 w0 = *(const float4*)(W1r + k * 128);
            float4 w1 = *(const float4*)(W1r + k * 128 + 4);
            u64 ws[8] = {splat2(w0.x), splat2(w0.y), splat2(w0.z), splat2(w0.w),
                         splat2(w1.x), splat2(w1.y), splat2(w1.z), splat2(w1.w)};
#pragma unroll
            for (int i = 0; i < 8; i++)
#pragma unroll
                for (int np = 0; np < 4; np++)
                    ffma2(acc[i * 4 + np], A2[np], ws[i]);
        }
    }
    __syncthreads();

    {
        float* Zs = sm;
#pragma unroll
        for (int i = 0; i < 8; i++) {
            int hh = th * 8 + i;
            int rot = hh >> 3;
            float* row = Zs + hh * 132;
#pragma unroll
            for (int np = 0; np < 4; np++) {
                u64 v = acc[i * 4 + np];
                u64 r = pack2(fmaxf(lo32(v), 0.f), fmaxf(hi32(v), 0.f));
                int q  = 2 * tn + (np >> 1);
                int qp = (q + rot) & 31;
                *(u64*)(row + qp * 4 + (np & 1) * 2) = r;
            }
        }
    }
    __syncthreads();

    u64 acc2[16];
#pragma unroll
    for (int o = 0; o < 4; o++) {
        u64 bo = splat2(sm[SM_B2 + th * 4 + o]);
#pragma unroll
        for (int np = 0; np < 4; np++) acc2[o * 4 + np] = bo;
    }
    {
        const float* Zs  = sm;
        const float* W2r = sm + SM_W2 + th * 4;
#pragma unroll 4
        for (int k = 0; k < 128; k++) {
            int rot = k >> 3;
            const float* row = Zs + k * 132;
            ulonglong2 z0 = *(const ulonglong2*)(row + (((2 * tn + 0 + rot) & 31) << 2));
            ulonglong2 z1 = *(const ulonglong2*)(row + (((2 * tn + 1 + rot) & 31) << 2));
            u64 A2[4] = {z0.x, z0.y, z1.x, z1.y};
            float4 wv = *(const float4*)(W2r + k * 64);
            u64 ws[4] = {splat2(wv.x), splat2(wv.y), splat2(wv.z), splat2(wv.w)};
#pragma unroll
            for (int o = 0; o < 4; o++)
#pragma unroll
                for (int np = 0; np < 4; np++)
                    ffma2(acc2[o * 4 + np], A2[np], ws[o]);
        }
    }

    u64 ss2[4];
#pragma unroll
    for (int np = 0; np < 4; np++) ss2[np] = 0ull;
#pragma unroll
    for (int o = 0; o < 4; o++)
#pragma unroll
        for (int np = 0; np < 4; np++)
            ffma2(ss2[np], acc2[o * 4 + np], acc2[o * 4 + np]);
#pragma unroll
    for (int m = 1; m < 16; m <<= 1)
#pragma unroll
        for (int np = 0; np < 4; np++)
            ss2[np] = add2(ss2[np], __shfl_xor_sync(0xffffffffu, ss2[np], m));

#pragma unroll
    for (int np = 0; np < 4; np++) {
        float se = 1.f / fmaxf(sqrtf(lo32(ss2[np])), 1e-12f);
        float so = 1.f / fmaxf(sqrtf(hi32(ss2[np])), 1e-12f);
        int ne = base + tn * 8 + 2 * np;
        if (ne < N_NODES) {
            float4 v;
            v.x = lo32(acc2[0 * 4 + np]) * se;
            v.y = lo32(acc2[1 * 4 + np]) * se;
            v.z = lo32(acc2[2 * 4 + np]) * se;
            v.w = lo32(acc2[3 * 4 + np]) * se;
            *(float4*)(out + ne * 64 + th * 4) = v;
        }
        if (ne + 1 < N_NODES) {
            float4 v;
            v.x = hi32(acc2[0 * 4 + np]) * so;
            v.y = hi32(acc2[1 * 4 + np]) * so;
            v.z = hi32(acc2[2 * 4 + np]) * so;
            v.w = hi32(acc2[3 * 4 + np]) * so;
            *(float4*)(out + (ne + 1) * 64 + th * 4) = v;
        }
    }
}

// ---------------- launch ----------------
extern "C" void kernel_launch(void* const* d_in, const int* in_sizes, int n_in,
                              void* d_out, int out_size) {
    const float* x  = (const float*)d_in[0];
    const int*   ei = (const int*)  d_in[1];
    const float* kw = (const float*)d_in[2];
    const float* W0 = (const float*)d_in[3];
    const float* b0 = (const float*)d_in[4];
    const float* W1 = (const float*)d_in[5];
    const float* b1 = (const float*)d_in[6];
    const float* W2 = (const float*)d_in[7];
    const float* b2 = (const float*)d_in[8];
    float* out = (float*)d_out;
    const int* src = ei;
    const int* dst = ei + N_EDGES;

    cudaFuncSetAttribute(k_mlp1, cudaFuncAttributeMaxDynamicSharedMemorySize,
                         SM_TOTAL * (int)sizeof(float));

    k_hist   <<<(N_EDGES + 255) / 256, 256>>>(dst);              // launch 0
    k_scan   <<<(N_NODES + 1023) / 1024, 1024>>>();              // launch 1
    k_scatter<<<(N_EDGES + 255) / 256, 256>>>(src, dst, kw);     // launch 2
    k_conv0  <<<N_NODES / 64, 256>>>(x, W0, b0);                 // launch 3 (ncu window)
    k_conv1  <<<N_NODES / 64, 256>>>();                          // launch 4
    k_mlp1   <<<(N_NODES + 127) / 128, 256, SM_TOTAL * (int)sizeof(float)>>>(W1, b1, W2, b2, out);
}

// round 12
// speedup vs baseline: 1.1679x; 1.0043x over previous
#include <cuda_runtime.h>
#include <math.h>

#define N_NODES 200000
#define N_EDGES 3200000

typedef unsigned long long u64;

// ---------------- static scratch ----------------
__device__ int      g_count [N_NODES];
__device__ int      g_rowptr[N_NODES + 1];
__device__ int      g_cursor[N_NODES];
__device__ u64      g_state [256];        // decoupled-lookback: (sum<<2)|flag
__device__ float4   g_sedge [N_EDGES];    // {src(bits), kw0, kw1, pad}
__device__ float    g_h     [N_NODES * 32];
__device__ float    g_agg1  [N_NODES * 64];

// ---------------- packed f32x2 helpers ----------------
__device__ __forceinline__ u64 splat2(float x) {
    u64 r; unsigned xi = __float_as_uint(x);
    asm("mov.b64 %0, {%1, %1};" : "=l"(r) : "r"(xi));
    return r;
}
__device__ __forceinline__ void ffma2(u64& d, u64 a, u64 b) {
    asm("fma.rn.f32x2 %0, %1, %2, %0;" : "+l"(d) : "l"(a), "l"(b));
}
__device__ __forceinline__ u64 add2(u64 a, u64 b) {
    u64 r; asm("add.rn.f32x2 %0, %1, %2;" : "=l"(r) : "l"(a), "l"(b));
    return r;
}
__device__ __forceinline__ float lo32(u64 v) { return __uint_as_float((unsigned)v); }
__device__ __forceinline__ float hi32(u64 v) { return __uint_as_float((unsigned)(v >> 32)); }
__device__ __forceinline__ u64 pack2(float lo, float hi) {
    return ((u64)__float_as_uint(hi) << 32) | (u64)__float_as_uint(lo);
}

// ---------------- CSR build ----------------
__global__ void k_hist(const int* __restrict__ dst) {
    int tid = threadIdx.x;
    if (blockIdx.x == 0 && tid < 256) g_state[tid] = 0ull;
    int e = blockIdx.x * blockDim.x + tid;
    if (e < N_EDGES) atomicAdd(&g_count[dst[e]], 1);
}

__global__ void __launch_bounds__(1024, 2) k_scan() {
    __shared__ int wsum[32];
    __shared__ int s_total;
    __shared__ int s_prefix;
    int tid = threadIdx.x, b = blockIdx.x;
    int i = b * 1024 + tid;
    int v = (i < N_NODES) ? g_count[i] : 0;
    if (i < N_NODES) g_count[i] = 0;
    int s = v;
#pragma unroll
    for (int o = 1; o < 32; o <<= 1) {
        int t = __shfl_up_sync(0xffffffffu, s, o);
        if ((tid & 31) >= o) s += t;
    }
    if ((tid & 31) == 31) wsum[tid >> 5] = s;
    __syncthreads();
    if (tid < 32) {
        int w = wsum[tid];
        int ws = w;
#pragma unroll
        for (int o = 1; o < 32; o <<= 1) {
            int t = __shfl_up_sync(0xffffffffu, ws, o);
            if (tid >= o) ws += t;
        }
        wsum[tid] = ws - w;
    }
    __syncthreads();
    int excl = s - v + wsum[tid >> 5];
    if (tid == 1023) s_total = excl + v;
    if (tid == 0) s_prefix = 0;
    __syncthreads();

    if (tid == 0) {
        u64 st = ((u64)s_total << 2) | (b == 0 ? 2ull : 1ull);
        atomicExch(&g_state[b], st);
        if (b == 0) g_rowptr[N_NODES] = N_EDGES;
    }
    if (b > 0 && tid < 32) {
        int run = 0, offset = 0;
        while (true) {
            int j = b - 1 - offset - tid;
            u64 st;
            if (j >= 0) {
                do { st = *(volatile u64*)&g_state[j]; } while ((st & 3ull) == 0ull);
            } else st = 2ull;
            unsigned pf = __ballot_sync(0xffffffffu, (st & 3ull) == 2ull);
            int contrib = (int)(st >> 2);
            if (pf) {
                int first = __ffs(pf) - 1;
                if (tid > first) contrib = 0;
#pragma unroll
                for (int o = 16; o; o >>= 1) contrib += __shfl_xor_sync(0xffffffffu, contrib, o);
                run += contrib;
                break;
            } else {
#pragma unroll
                for (int o = 16; o; o >>= 1) contrib += __shfl_xor_sync(0xffffffffu, contrib, o);
                run += contrib;
                offset += 32;
            }
        }
        if (tid == 0) {
            s_prefix = run;
            atomicExch(&g_state[b], (((u64)(run + s_total)) << 2) | 2ull);
        }
    }
    __syncthreads();
    if (i < N_NODES) {
        int val = excl + s_prefix;
        g_rowptr[i] = val;
        g_cursor[i] = val;
    }
}

__global__ void k_scatter(const int* __restrict__ src, const int* __restrict__ dst,
                          const float* __restrict__ kw) {
    int e = blockIdx.x * blockDim.x + threadIdx.x;
    if (e < N_EDGES) {
        int t = dst[e];
        int p = atomicAdd(&g_cursor[t], 1);
        float4 v;
        v.x = __int_as_float(src[e]);
        v.y = kw[e];
        v.z = kw[N_EDGES + e];
        v.w = 0.f;
        g_sedge[p] = v;
    }
}

// ---------------- fused conv0 + mlp0 + L2norm: 8 nodes per warp (imbalance averaging) ----------------
__global__ void k_conv0(const float* __restrict__ x,
                        const float* __restrict__ W0, const float* __restrict__ b0) {
    __shared__ float W0s[512];
    __shared__ float b0s[32];
    int tid = threadIdx.x;
    W0s[tid] = W0[tid];
    W0s[tid + 256] = W0[tid + 256];
    if (tid < 32) b0s[tid] = b0[tid];
    __syncthreads();

    int warp = tid >> 5, lane = tid & 31;
    int nodeBase = (blockIdx.x * 8 + warp) * 8;
    int f = lane & 7, sub = lane >> 3;

#pragma unroll 1
    for (int n = 0; n < 8; n++) {
        int node = nodeBase + n;
        int start = g_rowptr[node], end = g_rowptr[node + 1];
        float a0 = 0.f, a1 = 0.f;
        int e = start;
        for (; e + 8 <= end; e += 8) {
            float4 Ea = g_sedge[e + sub];
            float4 Eb = g_sedge[e + 4 + sub];
            float va = __ldg(&x[__float_as_int(Ea.x) * 8 + f]);
            float vb = __ldg(&x[__float_as_int(Eb.x) * 8 + f]);
            a0 = fmaf(Ea.y, va, a0); a1 = fmaf(Ea.z, va, a1);
            a0 = fmaf(Eb.y, vb, a0); a1 = fmaf(Eb.z, vb, a1);
        }
        for (; e + 4 <= end; e += 4) {
            float4 E = g_sedge[e + sub];
            float v = __ldg(&x[__float_as_int(E.x) * 8 + f]);
            a0 = fmaf(E.y, v, a0);
            a1 = fmaf(E.z, v, a1);
        }
        if (e + sub < end) {
            float4 E = g_sedge[e + sub];
            float v = __ldg(&x[__float_as_int(E.x) * 8 + f]);
            a0 = fmaf(E.y, v, a0);
            a1 = fmaf(E.z, v, a1);
        }
        a0 += __shfl_xor_sync(0xffffffffu, a0, 8);
        a0 += __shfl_xor_sync(0xffffffffu, a0, 16);
        a1 += __shfl_xor_sync(0xffffffffu, a1, 8);
        a1 += __shfl_xor_sync(0xffffffffu, a1, 16);

        float val = (lane & 8) ? a1 : a0;
        float acc = b0s[lane];
#pragma unroll
        for (int k = 0; k < 16; k++) {
            float ak = __shfl_sync(0xffffffffu, val, k);
            acc = fmaf(ak, W0s[k * 32 + lane], acc);
        }
        float ss = acc * acc;
#pragma unroll
        for (int o = 16; o; o >>= 1) ss += __shfl_xor_sync(0xffffffffu, ss, o);
        float sc = 1.f / fmaxf(sqrtf(ss), 1e-12f);
        g_h[node * 32 + lane] = acc * sc;
    }
}

// ---------------- layer 1 conv: 8 nodes per warp, lane = feature ----------------
__global__ void k_conv1() {
    int warp = threadIdx.x >> 5, lane = threadIdx.x & 31;
    int nodeBase = (blockIdx.x * 8 + warp) * 8;
    const float* __restrict__ h = g_h;

#pragma unroll 1
    for (int n = 0; n < 8; n++) {
        int node = nodeBase + n;
        int start = g_rowptr[node], end = g_rowptr[node + 1];
        float a0 = 0.f, a1 = 0.f;
        int e = start;
        for (; e + 8 <= end; e += 8) {
            float4 E0 = g_sedge[e],   E1 = g_sedge[e+1], E2 = g_sedge[e+2], E3 = g_sedge[e+3];
            float4 E4 = g_sedge[e+4], E5 = g_sedge[e+5], E6 = g_sedge[e+6], E7 = g_sedge[e+7];
            float v0 = h[__float_as_int(E0.x) * 32 + lane];
            float v1 = h[__float_as_int(E1.x) * 32 + lane];
            float v2 = h[__float_as_int(E2.x) * 32 + lane];
            float v3 = h[__float_as_int(E3.x) * 32 + lane];
            float v4 = h[__float_as_int(E4.x) * 32 + lane];
            float v5 = h[__float_as_int(E5.x) * 32 + lane];
            float v6 = h[__float_as_int(E6.x) * 32 + lane];
            float v7 = h[__float_as_int(E7.x) * 32 + lane];
            a0 = fmaf(E0.y, v0, a0); a1 = fmaf(E0.z, v0, a1);
            a0 = fmaf(E1.y, v1, a0); a1 = fmaf(E1.z, v1, a1);
            a0 = fmaf(E2.y, v2, a0); a1 = fmaf(E2.z, v2, a1);
            a0 = fmaf(E3.y, v3, a0); a1 = fmaf(E3.z, v3, a1);
            a0 = fmaf(E4.y, v4, a0); a1 = fmaf(E4.z, v4, a1);
            a0 = fmaf(E5.y, v5, a0); a1 = fmaf(E5.z, v5, a1);
            a0 = fmaf(E6.y, v6, a0); a1 = fmaf(E6.z, v6, a1);
            a0 = fmaf(E7.y, v7, a0); a1 = fmaf(E7.z, v7, a1);
        }
        for (; e + 4 <= end; e += 4) {
            float4 E0 = g_sedge[e], E1 = g_sedge[e+1], E2 = g_sedge[e+2], E3 = g_sedge[e+3];
            float v0 = h[__float_as_int(E0.x) * 32 + lane];
            float v1 = h[__float_as_int(E1.x) * 32 + lane];
            float v2 = h[__float_as_int(E2.x) * 32 + lane];
            float v3 = h[__float_as_int(E3.x) * 32 + lane];
            a0 = fmaf(E0.y, v0, a0); a1 = fmaf(E0.z, v0, a1);
            a0 = fmaf(E1.y, v1, a0); a1 = fmaf(E1.z, v1, a1);
            a0 = fmaf(E2.y, v2, a0); a1 = fmaf(E2.z, v2, a1);
            a0 = fmaf(E3.y, v3, a0); a1 = fmaf(E3.z, v3, a1);
        }
        for (; e < end; ++e) {
            float4 E = g_sedge[e];
            float v = h[__float_as_int(E.x) * 32 + lane];
            a0 = fmaf(E.y, v, a0);
            a1 = fmaf(E.z, v, a1);
        }
        g_agg1[node*64 + lane]      = a0;
        g_agg1[node*64 + 32 + lane] = a1;
    }
}

// ---------------- layer 1 MLP: register-tiled SGEMM, 8x8 tile/thread ----------------
#define SM_W1 0
#define SM_A  8192
#define SM_W2 16896
#define SM_B1 25088
#define SM_B2 25216
#define SM_TOTAL 25280

__global__ void __launch_bounds__(256, 2)
k_mlp1(const float* __restrict__ W1, const float* __restrict__ b1,
       const float* __restrict__ W2, const float* __restrict__ b2,
       float* __restrict__ out) {
    extern __shared__ float sm[];
    int tid = threadIdx.x;
    int th = tid & 15;
    int tn = tid >> 4;

    for (int i = tid; i < 8192; i += 256) {
        sm[SM_W1 + i] = W1[i];
        sm[SM_W2 + i] = W2[i];
    }
    if (tid < 128) sm[SM_B1 + tid] = b1[tid];
    if (tid < 64)  sm[SM_B2 + tid] = b2[tid];

    int base = blockIdx.x * 128;
    for (int idx = tid; idx < 8192; idx += 256) {
        int g = base * 64 + idx;
        float v = (g < N_NODES * 64) ? g_agg1[g] : 0.f;
        sm[SM_A + (idx & 63) * 132 + (idx >> 6)] = v;
    }
    __syncthreads();

    u64 acc[32];
#pragma unroll
    for (int i = 0; i < 8; i++) {
        u64 bi = splat2(sm[SM_B1 + th * 8 + i]);
#pragma unroll
        for (int np = 0; np < 4; np++) acc[i * 4 + np] = bi;
    }
    {
        const float* At  = sm + SM_A + tn * 8;
        const float* W1r = sm + SM_W1 + th * 8;
#pragma unroll 4
        for (int k = 0; k < 64; k++) {
            ulonglong2 avA = *(const ulonglong2*)(At + k * 132);
            ulonglong2 avB = *(const ulonglong2*)(At + k * 132 + 4);
            u64 A2[4] = {avA.x, avA.y, avB.x, avB.y};
            float4 w0 = *(const float4*)(W1r + k * 128);
            float4 w1 = *(const float4*)(W1r + k * 128 + 4);
            u64 ws[8] = {splat2(w0.x), splat2(w0.y), splat2(w0.z), splat2(w0.w),
                         splat2(w1.x), splat2(w1.y), splat2(w1.z), splat2(w1.w)};
#pragma unroll
            for (int i = 0; i < 8; i++)
#pragma unroll
                for (int np = 0; np < 4; np++)
                    ffma2(acc[i * 4 + np], A2[np], ws[i]);
        }
    }
    __syncthreads();

    {
        float* Zs = sm;
#pragma unroll
        for (int i = 0; i < 8; i++) {
            int hh = th * 8 + i;
            int rot = hh >> 3;
            float* row = Zs + hh * 132;
#pragma unroll
            for (int np = 0; np < 4; np++) {
                u64 v = acc[i * 4 + np];
                u64 r = pack2(fmaxf(lo32(v), 0.f), fmaxf(hi32(v), 0.f));
                int q  = 2 * tn + (np >> 1);
                int qp = (q + rot) & 31;
                *(u64*)(row + qp * 4 + (np & 1) * 2) = r;
            }
        }
    }
    __syncthreads();

    u64 acc2[16];
#pragma unroll
    for (int o = 0; o < 4; o++) {
        u64 bo = splat2(sm[SM_B2 + th * 4 + o]);
#pragma unroll
        for (int np = 0; np < 4; np++) acc2[o * 4 + np] = bo;
    }
    {
        const float* Zs  = sm;
        const float* W2r = sm + SM_W2 + th * 4;
#pragma unroll 4
        for (int k = 0; k < 128; k++) {
            int rot = k >> 3;
            const float* row = Zs + k * 132;
            ulonglong2 z0 = *(const ulonglong2*)(row + (((2 * tn + 0 + rot) & 31) << 2));
            ulonglong2 z1 = *(const ulonglong2*)(row + (((2 * tn + 1 + rot) & 31) << 2));
            u64 A2[4] = {z0.x, z0.y, z1.x, z1.y};
            float4 wv = *(const float4*)(W2r + k * 64);
            u64 ws[4] = {splat2(wv.x), splat2(wv.y), splat2(wv.z), splat2(wv.w)};
#pragma unroll
            for (int o = 0; o < 4; o++)
#pragma unroll
                for (int np = 0; np < 4; np++)
                    ffma2(acc2[o * 4 + np], A2[np], ws[o]);
        }
    }

    u64 ss2[4];
#pragma unroll
    for (int np = 0; np < 4; np++) ss2[np] = 0ull;
#pragma unroll
    for (int o = 0; o < 4; o++)
#pragma unroll
        for (int np = 0; np < 4; np++)
            ffma2(ss2[np], acc2[o * 4 + np], acc2[o * 4 + np]);
#pragma unroll
    for (int m = 1; m < 16; m <<= 1)
#pragma unroll
        for (int np = 0; np < 4; np++)
            ss2[np] = add2(ss2[np], __shfl_xor_sync(0xffffffffu, ss2[np], m));

#pragma unroll
    for (int np = 0; np < 4; np++) {
        float se = 1.f / fmaxf(sqrtf(lo32(ss2[np])), 1e-12f);
        float so = 1.f / fmaxf(sqrtf(hi32(ss2[np])), 1e-12f);
        int ne = base + tn * 8 + 2 * np;
        if (ne < N_NODES) {
            float4 v;
            v.x = lo32(acc2[0 * 4 + np]) * se;
            v.y = lo32(acc2[1 * 4 + np]) * se;
            v.z = lo32(acc2[2 * 4 + np]) * se;
            v.w = lo32(acc2[3 * 4 + np]) * se;
            *(float4*)(out + ne * 64 + th * 4) = v;
        }
        if (ne + 1 < N_NODES) {
            float4 v;
            v.x = hi32(acc2[0 * 4 + np]) * so;
            v.y = hi32(acc2[1 * 4 + np]) * so;
            v.z = hi32(acc2[2 * 4 + np]) * so;
            v.w = hi32(acc2[3 * 4 + np]) * so;
            *(float4*)(out + (ne + 1) * 64 + th * 4) = v;
        }
    }
}

// ---------------- launch ----------------
extern "C" void kernel_launch(void* const* d_in, const int* in_sizes, int n_in,
                              void* d_out, int out_size) {
    const float* x  = (const float*)d_in[0];
    const int*   ei = (const int*)  d_in[1];
    const float* kw = (const float*)d_in[2];
    const float* W0 = (const float*)d_in[3];
    const float* b0 = (const float*)d_in[4];
    const float* W1 = (const float*)d_in[5];
    const float* b1 = (const float*)d_in[6];
    const float* W2 = (const float*)d_in[7];
    const float* b2 = (const float*)d_in[8];
    float* out = (float*)d_out;
    const int* src = ei;
    const int* dst = ei + N_EDGES;

    cudaFuncSetAttribute(k_mlp1, cudaFuncAttributeMaxDynamicSharedMemorySize,
                         SM_TOTAL * (int)sizeof(float));

    k_hist   <<<(N_EDGES + 255) / 256, 256>>>(dst);              // launch 0
    k_scan   <<<(N_NODES + 1023) / 1024, 1024>>>();              // launch 1
    k_scatter<<<(N_EDGES + 255) / 256, 256>>>(src, dst, kw);     // launch 2
    k_conv0  <<<N_NODES / 64, 256>>>(x, W0, b0);                 // launch 3 (ncu window)
    k_conv1  <<<N_NODES / 64, 256>>>();                          // launch 4
    k_mlp1   <<<(N_NODES + 127) / 128, 256, SM_TOTAL * (int)sizeof(float)>>>(W1, b1, W2, b2, out);
}